// round 7
// baseline (speedup 1.0000x reference)
#include <cuda_runtime.h>
#include <cuda_bf16.h>
#include <math.h>
#include <stdint.h>

#define BB 2
#define NN 2048
#define KK 48
#define CC 128
#define FFD 512
#define BN (BB * NN)
#define EPSLN 1e-5f
#define INV_SCALE (1.0f / 30.0f)

// ---------------- device scratch ----------------
__device__ float g_Pa[BN * CC];   // h_V @ W1a + b1
__device__ float g_Pc[BN * CC];   // h_V @ W1c
__device__ float g_dh[BN * CC];   // masked message sum
__device__ __nv_bfloat16 g_Wimg[12 * 16384];

__device__ __forceinline__ float gelu_f(float x) {
    return 0.5f * x * (1.0f + erff(x * 0.70710678118654752f));
}
__device__ __forceinline__ void split_pack(float a, float b, uint32_t& hi, uint32_t& lo) {
    __nv_bfloat16 ah = __float2bfloat16_rn(a);
    __nv_bfloat16 bh = __float2bfloat16_rn(b);
    __nv_bfloat162 hp; hp.x = ah; hp.y = bh;
    __nv_bfloat162 lp;
    lp.x = __float2bfloat16_rn(a - __bfloat162float(ah));
    lp.y = __float2bfloat16_rn(b - __bfloat162float(bh));
    hi = *reinterpret_cast<uint32_t*>(&hp);
    lo = *reinterpret_cast<uint32_t*>(&lp);
}
__device__ __forceinline__ void mma16816(float c[4], const uint32_t a[4],
                                         uint32_t b0, uint32_t b1) {
    asm volatile(
        "mma.sync.aligned.m16n8k16.row.col.f32.bf16.bf16.f32 "
        "{%0,%1,%2,%3}, {%4,%5,%6,%7}, {%8,%9}, {%0,%1,%2,%3};"
        : "+f"(c[0]), "+f"(c[1]), "+f"(c[2]), "+f"(c[3])
        : "r"(a[0]), "r"(a[1]), "r"(a[2]), "r"(a[3]), "r"(b0), "r"(b1));
}

// ---------------------------------------------------------------------------
// Weight prep: 12 images in HMMA B-fragment order (unchanged, proven).
// ---------------------------------------------------------------------------
__global__ void prep_weights(const float* __restrict__ A0, const float* __restrict__ A1,
                             const float* __restrict__ A2, const float* __restrict__ B0,
                             const float* __restrict__ B1, const float* __restrict__ B2) {
    const float* srcs[6] = {A0, A1, A2, B0, B1, B2};
    int img = blockIdx.x;
    int set = img / 6, layer = (img % 6) >> 1, split = img & 1;
    const float* s = srcs[set * 3 + layer];
    __nv_bfloat16* dst = g_Wimg + (size_t)img * 16384;
    for (int e = threadIdx.x; e < 16384; e += blockDim.x) {
        int k = e >> 7, n = e & 127;
        float val = s[e];
        __nv_bfloat16 h = __float2bfloat16_rn(val);
        __nv_bfloat16 outv = split ? __float2bfloat16_rn(val - __bfloat162float(h)) : h;
        int kk = k & 15;
        int t = (kk & 7) >> 1, hi8 = kk >> 3, idx = kk & 1;
        int lane = (n & 7) * 4 + t;
        int chunk = (n >> 3) * 8 + (k >> 4);
        dst[chunk * 128 + lane * 4 + hi8 * 2 + idx] = outv;
    }
}

// ---------------------------------------------------------------------------
// HMMA edge MLP, software-pipelined.
// ---------------------------------------------------------------------------
#define A_STRIDE_W 68
#define A_WORDS (KK * A_STRIDE_W)
#define SMEM_W_BYTES 196608
#define SMEM_EDGE_DYN (SMEM_W_BYTES + 2 * A_WORDS * 4)

template <bool EDGE_OUT>
__global__ void __launch_bounds__(384, 1) edge_mma_kernel(
    const float* __restrict__ h_E, const int* __restrict__ E_idx,
    const float* __restrict__ mask_attend, int wset,
    const float* __restrict__ b2v, const float* __restrict__ b3v,
    const float* __restrict__ g3v, const float* __restrict__ b3ln,
    float* __restrict__ outp) {
    extern __shared__ uint32_t smem[];
    uint32_t* smW = smem;
    uint32_t* smA = smem + (SMEM_W_BYTES / 4);
    float* Fs = (float*)smA;

    __shared__ int s_idx[KK];
    __shared__ float s_mask[KK];
    __shared__ float s_b2[CC], s_b3[CC], s_g3[CC], s_bl[CC];
    __shared__ float s_red[KK][4][2];

    const int tid = threadIdx.x, lane = tid & 31, wid = tid >> 5;
    const int g = lane >> 2, t = lane & 3;
    const int mtile = wid >> 2, nchunk = wid & 3;
    const int m0 = mtile * 16, n0 = nchunk * 32;
    const int ntg0 = nchunk * 4;

    {
        const float4* src = (const float4*)(g_Wimg + (size_t)wset * 6 * 16384);
        float4* dst = (float4*)smW;
        for (int i = tid; i < 12288; i += 384) dst[i] = src[i];
    }
    if (tid < CC) {
        s_b2[tid] = b2v[tid];
        s_b3[tid] = b3v[tid];
        if (EDGE_OUT) { s_g3[tid] = g3v[tid]; s_bl[tid] = b3ln[tid]; }
    }

    const int r_lo = m0 + g, r_hi = m0 + g + 8;

    // prefetch first node's h_E tile into registers
    float4 r_he[4];
    int node = blockIdx.x;
    if (node < BN) {
        const float4* he4 = (const float4*)(h_E + (size_t)node * (KK * CC));
#pragma unroll
        for (int i = 0; i < 4; ++i) r_he[i] = he4[tid + 384 * i];
    }

    for (; node < BN; node += gridDim.x) {
        __syncthreads();   // previous iteration's smA reads complete

        if (tid < KK) {
            s_idx[tid] = E_idx[node * KK + tid];
            s_mask[tid] = mask_attend[node * KK + tid];
        }
#pragma unroll
        for (int i = 0; i < 4; ++i) {
            int idx4 = tid + 384 * i;
            float4 v = r_he[i];
            int row = idx4 >> 5, colw = (idx4 & 31) * 2;
            uint32_t h0, l0, h1, l1;
            split_pack(v.x, v.y, h0, l0);
            split_pack(v.z, v.w, h1, l1);
            int w = row * A_STRIDE_W + colw;
            smA[w] = h0; smA[w + 1] = h1;
            smA[A_WORDS + w] = l0; smA[A_WORDS + w + 1] = l1;
        }
        __syncthreads();

        // prefetch Pa + neighbor Pc rows for layer-0 epilogue
        float2 pfa[4], pf0[4], pf1[4];
        {
            int gb = (node >> 11) * NN;
            int nbr0 = gb + s_idx[r_lo];
            int nbr1 = gb + s_idx[r_hi];
#pragma unroll
            for (int nt = 0; nt < 4; ++nt) {
                int c = n0 + nt * 8 + t * 2;
                pfa[nt] = *(const float2*)(g_Pa + (size_t)node * CC + c);
                pf0[nt] = *(const float2*)(g_Pc + (size_t)nbr0 * CC + c);
                pf1[nt] = *(const float2*)(g_Pc + (size_t)nbr1 * CC + c);
            }
        }

        for (int layer = 0; layer < 3; ++layer) {
            // prefetch next node's h_E during last layer's MMA
            if (layer == 2) {
                int nn = node + gridDim.x;
                if (nn < BN) {
                    const float4* he4 = (const float4*)(h_E + (size_t)nn * (KK * CC));
#pragma unroll
                    for (int i = 0; i < 4; ++i) r_he[i] = he4[tid + 384 * i];
                }
            }

            float acc[4][4];
#pragma unroll
            for (int nt = 0; nt < 4; ++nt)
#pragma unroll
                for (int j = 0; j < 4; ++j) acc[nt][j] = 0.0f;

            const uint2* WH = (const uint2*)(smW + (layer * 2) * 8192);
            const uint2* WL = WH + 4096;
#pragma unroll
            for (int ks = 0; ks < 8; ++ks) {
                uint32_t ahi[4], alo[4];
                int aw = r_lo * A_STRIDE_W + ks * 8 + t;
                int aw2 = r_hi * A_STRIDE_W + ks * 8 + t;
                ahi[0] = smA[aw];        ahi[1] = smA[aw2];
                ahi[2] = smA[aw + 4];    ahi[3] = smA[aw2 + 4];
                alo[0] = smA[A_WORDS + aw];     alo[1] = smA[A_WORDS + aw2];
                alo[2] = smA[A_WORDS + aw + 4]; alo[3] = smA[A_WORDS + aw2 + 4];
#pragma unroll
                for (int nt = 0; nt < 4; ++nt) {
                    int chunk = (ntg0 + nt) * 8 + ks;
                    uint2 bh = WH[chunk * 32 + lane];
                    uint2 bl = WL[chunk * 32 + lane];
                    mma16816(acc[nt], ahi, bh.x, bh.y);
                    mma16816(acc[nt], alo, bh.x, bh.y);
                    mma16816(acc[nt], ahi, bl.x, bl.y);
                }
            }
            __syncthreads();   // all A reads done before rewrite

            if (layer < 2) {
#pragma unroll
                for (int nt = 0; nt < 4; ++nt) {
                    int c = n0 + nt * 8 + t * 2;
                    float a0, a1, b0, b1;
                    if (layer == 0) {
                        a0 = pfa[nt].x + pf0[nt].x; a1 = pfa[nt].y + pf0[nt].y;
                        b0 = pfa[nt].x + pf1[nt].x; b1 = pfa[nt].y + pf1[nt].y;
                    } else {
                        a0 = s_b2[c]; a1 = s_b2[c + 1];
                        b0 = a0; b1 = a1;
                    }
                    float xl0 = gelu_f(acc[nt][0] + a0);
                    float xl1 = gelu_f(acc[nt][1] + a1);
                    float xh0 = gelu_f(acc[nt][2] + b0);
                    float xh1 = gelu_f(acc[nt][3] + b1);
                    uint32_t hh, ll;
                    int w0 = r_lo * A_STRIDE_W + c / 2;
                    int w1 = r_hi * A_STRIDE_W + c / 2;
                    split_pack(xl0, xl1, hh, ll);
                    smA[w0] = hh; smA[A_WORDS + w0] = ll;
                    split_pack(xh0, xh1, hh, ll);
                    smA[w1] = hh; smA[A_WORDS + w1] = ll;
                }
                __syncthreads();
            } else if (!EDGE_OUT) {
                float mlo = s_mask[r_lo], mhi = s_mask[r_hi];
#pragma unroll
                for (int nt = 0; nt < 4; ++nt) {
                    int c = n0 + nt * 8 + t * 2;
                    float2 v0, v1;
                    v0.x = mlo * (acc[nt][0] + s_b3[c]);
                    v0.y = mlo * (acc[nt][1] + s_b3[c + 1]);
                    v1.x = mhi * (acc[nt][2] + s_b3[c]);
                    v1.y = mhi * (acc[nt][3] + s_b3[c + 1]);
                    *(float2*)(Fs + r_lo * 132 + c) = v0;
                    *(float2*)(Fs + r_hi * 132 + c) = v1;
                }
                __syncthreads();
                if (tid < CC) {
                    float s = 0.0f;
#pragma unroll
                    for (int r = 0; r < KK; ++r) s += Fs[r * 132 + tid];
                    g_dh[(size_t)node * CC + tid] = s;
                }
            } else {
                const float* he = h_E + (size_t)node * (KK * CC);
                float v[4][4];
                float sl = 0.0f, ql = 0.0f, sh = 0.0f, qh = 0.0f;
#pragma unroll
                for (int nt = 0; nt < 4; ++nt) {
                    int c = n0 + nt * 8 + t * 2;
                    float2 e0 = *(const float2*)(he + r_lo * CC + c);
                    float2 e1 = *(const float2*)(he + r_hi * CC + c);
                    v[nt][0] = acc[nt][0] + s_b3[c] + e0.x;
                    v[nt][1] = acc[nt][1] + s_b3[c + 1] + e0.y;
                    v[nt][2] = acc[nt][2] + s_b3[c] + e1.x;
                    v[nt][3] = acc[nt][3] + s_b3[c + 1] + e1.y;
                    sl += v[nt][0] + v[nt][1]; ql += v[nt][0] * v[nt][0] + v[nt][1] * v[nt][1];
                    sh += v[nt][2] + v[nt][3]; qh += v[nt][2] * v[nt][2] + v[nt][3] * v[nt][3];
                }
#pragma unroll
                for (int off = 1; off <= 2; off <<= 1) {
                    sl += __shfl_xor_sync(0xffffffffu, sl, off);
                    ql += __shfl_xor_sync(0xffffffffu, ql, off);
                    sh += __shfl_xor_sync(0xffffffffu, sh, off);
                    qh += __shfl_xor_sync(0xffffffffu, qh, off);
                }
                if (t == 0) {
                    s_red[r_lo][nchunk][0] = sl; s_red[r_lo][nchunk][1] = ql;
                    s_red[r_hi][nchunk][0] = sh; s_red[r_hi][nchunk][1] = qh;
                }
                __syncthreads();
                float S0 = 0, Q0 = 0, S1 = 0, Q1 = 0;
#pragma unroll
                for (int w = 0; w < 4; ++w) {
                    S0 += s_red[r_lo][w][0]; Q0 += s_red[r_lo][w][1];
                    S1 += s_red[r_hi][w][0]; Q1 += s_red[r_hi][w][1];
                }
                float m0f = S0 * (1.0f / 128.0f);
                float rs0 = rsqrtf(Q0 * (1.0f / 128.0f) - m0f * m0f + EPSLN);
                float m1f = S1 * (1.0f / 128.0f);
                float rs1 = rsqrtf(Q1 * (1.0f / 128.0f) - m1f * m1f + EPSLN);
                float* op = outp + (size_t)node * (KK * CC);
#pragma unroll
                for (int nt = 0; nt < 4; ++nt) {
                    int c = n0 + nt * 8 + t * 2;
                    float2 o0, o1;
                    o0.x = s_g3[c] * (v[nt][0] - m0f) * rs0 + s_bl[c];
                    o0.y = s_g3[c + 1] * (v[nt][1] - m0f) * rs0 + s_bl[c + 1];
                    o1.x = s_g3[c] * (v[nt][2] - m1f) * rs1 + s_bl[c];
                    o1.y = s_g3[c + 1] * (v[nt][3] - m1f) * rs1 + s_bl[c + 1];
                    *(float2*)(op + r_lo * CC + c) = o0;
                    *(float2*)(op + r_hi * CC + c) = o1;
                }
            }
        }
    }
}

// ---------------------------------------------------------------------------
// Scalar node kernels, re-tiled to 16 nodes/block for occupancy (2 CTA/SM).
// ---------------------------------------------------------------------------
template <int R>
__device__ __forceinline__ void mm_tile(float acc[R][4], const float* Xs, int xstride4,
                                        const float* Ws, int r0, int lane) {
    const float4* X4 = (const float4*)Xs;
    const float4* W4 = (const float4*)Ws;
#pragma unroll 4
    for (int kq = 0; kq < 32; ++kq) {
        float4 w0 = W4[(4 * kq + 0) * 32 + lane];
        float4 w1 = W4[(4 * kq + 1) * 32 + lane];
        float4 w2 = W4[(4 * kq + 2) * 32 + lane];
        float4 w3 = W4[(4 * kq + 3) * 32 + lane];
#pragma unroll
        for (int i = 0; i < R; ++i) {
            float4 x = X4[(r0 + i) * xstride4 + kq];
            acc[i][0] = fmaf(x.x, w0.x, acc[i][0]); acc[i][1] = fmaf(x.x, w0.y, acc[i][1]);
            acc[i][2] = fmaf(x.x, w0.z, acc[i][2]); acc[i][3] = fmaf(x.x, w0.w, acc[i][3]);
            acc[i][0] = fmaf(x.y, w1.x, acc[i][0]); acc[i][1] = fmaf(x.y, w1.y, acc[i][1]);
            acc[i][2] = fmaf(x.y, w1.z, acc[i][2]); acc[i][3] = fmaf(x.y, w1.w, acc[i][3]);
            acc[i][0] = fmaf(x.z, w2.x, acc[i][0]); acc[i][1] = fmaf(x.z, w2.y, acc[i][1]);
            acc[i][2] = fmaf(x.z, w2.z, acc[i][2]); acc[i][3] = fmaf(x.z, w2.w, acc[i][3]);
            acc[i][0] = fmaf(x.w, w3.x, acc[i][0]); acc[i][1] = fmaf(x.w, w3.y, acc[i][1]);
            acc[i][2] = fmaf(x.w, w3.z, acc[i][2]); acc[i][3] = fmaf(x.w, w3.w, acc[i][3]);
        }
    }
}

__global__ void __launch_bounds__(512, 2) nodepre_kernel(
    const float* __restrict__ hV, const float* __restrict__ W1,
    const float* __restrict__ b1) {
    extern __shared__ float sm[];
    float* Vs = sm;           // 16*128
    float* Ws = sm + 2048;    // 128*128
    int tid = threadIdx.x, lane = tid & 31, warp = tid >> 5;
    size_t base = (size_t)blockIdx.x * 16 * CC;

    ((float4*)Vs)[tid] = ((const float4*)(hV + base))[tid & 511];
    {
        const float4* src = (const float4*)W1;
        float4* dst = (float4*)Ws;
#pragma unroll
        for (int e = 0; e < 8; ++e) dst[tid + 512 * e] = src[tid + 512 * e];
    }
    __syncthreads();

    int c0 = lane * 4;
    float acc[1][4];
#pragma unroll
    for (int j = 0; j < 4; ++j) acc[0][j] = b1[c0 + j];
    mm_tile<1>(acc, Vs, 32, Ws, warp, lane);
#pragma unroll
    for (int j = 0; j < 4; ++j)
        g_Pa[base + (size_t)warp * CC + c0 + j] = acc[0][j];
    __syncthreads();
    {
        const float4* src = (const float4*)(W1 + 2 * CC * CC);
        float4* dst = (float4*)Ws;
#pragma unroll
        for (int e = 0; e < 8; ++e) dst[tid + 512 * e] = src[tid + 512 * e];
    }
    __syncthreads();
#pragma unroll
    for (int j = 0; j < 4; ++j) acc[0][j] = 0.0f;
    mm_tile<1>(acc, Vs, 32, Ws, warp, lane);
#pragma unroll
    for (int j = 0; j < 4; ++j)
        g_Pc[base + (size_t)warp * CC + c0 + j] = acc[0][j];
}

__global__ void __launch_bounds__(512, 2) ffn_kernel(
    const float* __restrict__ hV,
    const float* __restrict__ Win_w, const float* __restrict__ Win_b,
    const float* __restrict__ Wout_w, const float* __restrict__ Wout_b,
    const float* __restrict__ g1, const float* __restrict__ b1,
    const float* __restrict__ g2, const float* __restrict__ b2,
    const float* __restrict__ mask_V, float* __restrict__ out) {
    extern __shared__ float sm[];
    float* V1s = sm;                 // 16*128
    float* Ts = sm + 2048;           // 16*512
    float* Ws = sm + 2048 + 8192;    // 128*128
    int tid = threadIdx.x, lane = tid & 31, warp = tid >> 5;
    size_t base = (size_t)blockIdx.x * 16 * CC;
    int c0 = lane * 4;
    int r = warp;   // one row per warp (16 warps, 16 nodes)

    {
        float4 xv = *(const float4*)(hV + base + (size_t)r * CC + c0);
        float4 dv = *(const float4*)(&g_dh[base + (size_t)r * CC + c0]);
        float x0 = xv.x + dv.x * INV_SCALE, x1 = xv.y + dv.y * INV_SCALE;
        float x2 = xv.z + dv.z * INV_SCALE, x3 = xv.w + dv.w * INV_SCALE;
        float s = x0 + x1 + x2 + x3;
        float q = x0 * x0 + x1 * x1 + x2 * x2 + x3 * x3;
#pragma unroll
        for (int off = 16; off; off >>= 1) {
            s += __shfl_xor_sync(0xffffffffu, s, off);
            q += __shfl_xor_sync(0xffffffffu, q, off);
        }
        float mean = s * (1.0f / 128.0f);
        float var = q * (1.0f / 128.0f) - mean * mean;
        float rs = rsqrtf(var + EPSLN);
        float4 o;
        o.x = g1[c0 + 0] * (x0 - mean) * rs + b1[c0 + 0];
        o.y = g1[c0 + 1] * (x1 - mean) * rs + b1[c0 + 1];
        o.z = g1[c0 + 2] * (x2 - mean) * rs + b1[c0 + 2];
        o.w = g1[c0 + 3] * (x3 - mean) * rs + b1[c0 + 3];
        *(float4*)(V1s + r * CC + c0) = o;
    }
    __syncthreads();
    for (int ct = 0; ct < 4; ++ct) {
        if (ct) __syncthreads();
        for (int e = tid; e < 4096; e += 512) {
            int k = e >> 5, cq = e & 31;
            ((float4*)Ws)[e] = ((const float4*)Win_w)[k * 128 + ct * 32 + cq];
        }
        __syncthreads();
        float acc[1][4];
#pragma unroll
        for (int j = 0; j < 4; ++j) acc[0][j] = Win_b[ct * 128 + c0 + j];
        mm_tile<1>(acc, V1s, 32, Ws, r, lane);
#pragma unroll
        for (int j = 0; j < 4; ++j)
            Ts[r * FFD + ct * 128 + c0 + j] = gelu_f(acc[0][j]);
    }
    __syncthreads();
    float acc[1][4];
#pragma unroll
    for (int j = 0; j < 4; ++j) acc[0][j] = Wout_b[c0 + j];
    for (int kt = 0; kt < 4; ++kt) {
        if (kt) __syncthreads();
        for (int e = tid; e < 4096; e += 512)
            ((float4*)Ws)[e] = ((const float4*)Wout_w)[kt * 4096 + e];
        __syncthreads();
        mm_tile<1>(acc, Ts + kt * 128, 128, Ws, r, lane);
    }
    {
        float v0 = V1s[r * CC + c0 + 0] + acc[0][0];
        float v1 = V1s[r * CC + c0 + 1] + acc[0][1];
        float v2 = V1s[r * CC + c0 + 2] + acc[0][2];
        float v3 = V1s[r * CC + c0 + 3] + acc[0][3];
        float s = v0 + v1 + v2 + v3;
        float q = v0 * v0 + v1 * v1 + v2 * v2 + v3 * v3;
#pragma unroll
        for (int off = 16; off; off >>= 1) {
            s += __shfl_xor_sync(0xffffffffu, s, off);
            q += __shfl_xor_sync(0xffffffffu, q, off);
        }
        float mean = s * (1.0f / 128.0f);
        float var = q * (1.0f / 128.0f) - mean * mean;
        float rs = rsqrtf(var + EPSLN);
        float mv = mask_V[blockIdx.x * 16 + r];
        float4 o;
        o.x = (g2[c0 + 0] * (v0 - mean) * rs + b2[c0 + 0]) * mv;
        o.y = (g2[c0 + 1] * (v1 - mean) * rs + b2[c0 + 1]) * mv;
        o.z = (g2[c0 + 2] * (v2 - mean) * rs + b2[c0 + 2]) * mv;
        o.w = (g2[c0 + 3] * (v3 - mean) * rs + b2[c0 + 3]) * mv;
        *(float4*)(out + base + (size_t)r * CC + c0) = o;
    }
}

// ---------------------------------------------------------------------------
extern "C" void kernel_launch(void* const* d_in, const int* in_sizes, int n_in,
                              void* d_out, int out_size) {
    const float* h_V = (const float*)d_in[0];
    const float* h_E = (const float*)d_in[1];
    const int* E_idx = (const int*)d_in[2];
    const float* mask_V = (const float*)d_in[3];
    const float* mask_attend = (const float*)d_in[4];
    const float* W1_w = (const float*)d_in[5];
    const float* W1_b = (const float*)d_in[6];
    const float* W2_w = (const float*)d_in[7];
    const float* W2_b = (const float*)d_in[8];
    const float* W3_w = (const float*)d_in[9];
    const float* W3_b = (const float*)d_in[10];
    const float* W11_w = (const float*)d_in[11];
    const float* W11_b = (const float*)d_in[12];
    const float* W12_w = (const float*)d_in[13];
    const float* W12_b = (const float*)d_in[14];
    const float* W13_w = (const float*)d_in[15];
    const float* W13_b = (const float*)d_in[16];
    const float* Win_w = (const float*)d_in[17];
    const float* Win_b = (const float*)d_in[18];
    const float* Wout_w = (const float*)d_in[19];
    const float* Wout_b = (const float*)d_in[20];
    const float* g1 = (const float*)d_in[21];
    const float* b1 = (const float*)d_in[22];
    const float* g2 = (const float*)d_in[23];
    const float* b2 = (const float*)d_in[24];
    const float* g3 = (const float*)d_in[25];
    const float* b3 = (const float*)d_in[26];

    float* out_hV = (float*)d_out;
    float* out_hE = out_hV + (size_t)BN * CC;

    const int SMEM_PRE = (2048 + 16384) * 4;          // 72 KB
    const int SMEM_FFN = (2048 + 8192 + 16384) * 4;   // 104 KB

    cudaFuncSetAttribute(nodepre_kernel, cudaFuncAttributeMaxDynamicSharedMemorySize, SMEM_PRE);
    cudaFuncSetAttribute(ffn_kernel, cudaFuncAttributeMaxDynamicSharedMemorySize, SMEM_FFN);
    cudaFuncSetAttribute(edge_mma_kernel<false>, cudaFuncAttributeMaxDynamicSharedMemorySize, SMEM_EDGE_DYN);
    cudaFuncSetAttribute(edge_mma_kernel<true>, cudaFuncAttributeMaxDynamicSharedMemorySize, SMEM_EDGE_DYN);

    prep_weights<<<12, 256>>>(W1_w + CC * CC, W2_w, W3_w, W11_w + CC * CC, W12_w, W13_w);
    nodepre_kernel<<<BN / 16, 512, SMEM_PRE>>>(h_V, W1_w, W1_b);
    edge_mma_kernel<false><<<148, 384, SMEM_EDGE_DYN>>>(h_E, E_idx, mask_attend, 0,
                                                        W2_b, W3_b, g3, b3, out_hE);
    ffn_kernel<<<BN / 16, 512, SMEM_FFN>>>(h_V, Win_w, Win_b, Wout_w, Wout_b,
                                           g1, b1, g2, b2, mask_V, out_hV);
    nodepre_kernel<<<BN / 16, 512, SMEM_PRE>>>(out_hV, W11_w, W11_b);
    edge_mma_kernel<true><<<148, 384, SMEM_EDGE_DYN>>>(h_E, E_idx, mask_attend, 1,
                                                       W12_b, W13_b, g3, b3, out_hE);
}

// round 9
// speedup vs baseline: 1.0437x; 1.0437x over previous
#include <cuda_runtime.h>
#include <cuda_bf16.h>
#include <math.h>
#include <stdint.h>

#define BB 2
#define NN 2048
#define KK 48
#define CC 128
#define FFD 512
#define BN (BB * NN)
#define EPSLN 1e-5f
#define INV_SCALE (1.0f / 30.0f)

// ---------------- device scratch ----------------
__device__ float g_Pa[BN * CC];   // h_V @ W1a + b1
__device__ float g_Pc[BN * CC];   // h_V @ W1c
__device__ float g_dh[BN * CC];   // masked message sum
__device__ __nv_bfloat16 g_Wimg[12 * 16384];

__device__ __forceinline__ float gelu_f(float x) {
    return 0.5f * x * (1.0f + erff(x * 0.70710678118654752f));
}
__device__ __forceinline__ void split_pack(float a, float b, uint32_t& hi, uint32_t& lo) {
    __nv_bfloat16 ah = __float2bfloat16_rn(a);
    __nv_bfloat16 bh = __float2bfloat16_rn(b);
    __nv_bfloat162 hp; hp.x = ah; hp.y = bh;
    __nv_bfloat162 lp;
    lp.x = __float2bfloat16_rn(a - __bfloat162float(ah));
    lp.y = __float2bfloat16_rn(b - __bfloat162float(bh));
    hi = *reinterpret_cast<uint32_t*>(&hp);
    lo = *reinterpret_cast<uint32_t*>(&lp);
}
__device__ __forceinline__ void mma16816(float c[4], const uint32_t a[4],
                                         uint32_t b0, uint32_t b1) {
    asm volatile(
        "mma.sync.aligned.m16n8k16.row.col.f32.bf16.bf16.f32 "
        "{%0,%1,%2,%3}, {%4,%5,%6,%7}, {%8,%9}, {%0,%1,%2,%3};"
        : "+f"(c[0]), "+f"(c[1]), "+f"(c[2]), "+f"(c[3])
        : "r"(a[0]), "r"(a[1]), "r"(a[2]), "r"(a[3]), "r"(b0), "r"(b1));
}

// ---------------------------------------------------------------------------
// Weight prep: 12 images in HMMA B-fragment order (proven).
// ---------------------------------------------------------------------------
__global__ void prep_weights(const float* __restrict__ A0, const float* __restrict__ A1,
                             const float* __restrict__ A2, const float* __restrict__ B0,
                             const float* __restrict__ B1, const float* __restrict__ B2) {
    const float* srcs[6] = {A0, A1, A2, B0, B1, B2};
    int img = blockIdx.x;
    int set = img / 6, layer = (img % 6) >> 1, split = img & 1;
    const float* s = srcs[set * 3 + layer];
    __nv_bfloat16* dst = g_Wimg + (size_t)img * 16384;
    for (int e = threadIdx.x; e < 16384; e += blockDim.x) {
        int k = e >> 7, n = e & 127;
        float val = s[e];
        __nv_bfloat16 h = __float2bfloat16_rn(val);
        __nv_bfloat16 outv = split ? __float2bfloat16_rn(val - __bfloat162float(h)) : h;
        int kk = k & 15;
        int t = (kk & 7) >> 1, hi8 = kk >> 3, idx = kk & 1;
        int lane = (n & 7) * 4 + t;
        int chunk = (n >> 3) * 8 + (k >> 4);
        dst[chunk * 128 + lane * 4 + hi8 * 2 + idx] = outv;
    }
}

// ---------------------------------------------------------------------------
// HMMA edge MLP — split accumulators (acc_h/acc_l/acc_m) to break RAW chains.
// ---------------------------------------------------------------------------
#define A_STRIDE_W 68
#define A_WORDS (KK * A_STRIDE_W)
#define SMEM_W_BYTES 196608
#define SMEM_EDGE_DYN (SMEM_W_BYTES + 2 * A_WORDS * 4)

template <bool EDGE_OUT>
__global__ void __launch_bounds__(384, 1) edge_mma_kernel(
    const float* __restrict__ h_E, const int* __restrict__ E_idx,
    const float* __restrict__ mask_attend, int wset,
    const float* __restrict__ b2v, const float* __restrict__ b3v,
    const float* __restrict__ g3v, const float* __restrict__ b3ln,
    float* __restrict__ outp) {
    extern __shared__ uint32_t smem[];
    uint32_t* smW = smem;
    uint32_t* smA = smem + (SMEM_W_BYTES / 4);
    float* Fs = (float*)smA;

    __shared__ int s_idx[KK];
    __shared__ float s_mask[KK];
    __shared__ float s_b2[CC], s_b3[CC], s_g3[CC], s_bl[CC];
    __shared__ float s_red[KK][4][2];

    const int tid = threadIdx.x, lane = tid & 31, wid = tid >> 5;
    const int g = lane >> 2, t = lane & 3;
    const int mtile = wid >> 2, nchunk = wid & 3;
    const int m0 = mtile * 16, n0 = nchunk * 32;
    const int ntg0 = nchunk * 4;

    {
        const float4* src = (const float4*)(g_Wimg + (size_t)wset * 6 * 16384);
        float4* dst = (float4*)smW;
        for (int i = tid; i < 12288; i += 384) dst[i] = src[i];
    }
    if (tid < CC) {
        s_b2[tid] = b2v[tid];
        s_b3[tid] = b3v[tid];
        if (EDGE_OUT) { s_g3[tid] = g3v[tid]; s_bl[tid] = b3ln[tid]; }
    }

    const int r_lo = m0 + g, r_hi = m0 + g + 8;

    // prefetch first node's h_E tile into registers
    float4 r_he[4];
    int node = blockIdx.x;
    if (node < BN) {
        const float4* he4 = (const float4*)(h_E + (size_t)node * (KK * CC));
#pragma unroll
        for (int i = 0; i < 4; ++i) r_he[i] = he4[tid + 384 * i];
    }

    for (; node < BN; node += gridDim.x) {
        __syncthreads();

        if (tid < KK) {
            s_idx[tid] = E_idx[node * KK + tid];
            s_mask[tid] = mask_attend[node * KK + tid];
        }
#pragma unroll
        for (int i = 0; i < 4; ++i) {
            int idx4 = tid + 384 * i;
            float4 v = r_he[i];
            int row = idx4 >> 5, colw = (idx4 & 31) * 2;
            uint32_t h0, l0, h1, l1;
            split_pack(v.x, v.y, h0, l0);
            split_pack(v.z, v.w, h1, l1);
            int w = row * A_STRIDE_W + colw;
            smA[w] = h0; smA[w + 1] = h1;
            smA[A_WORDS + w] = l0; smA[A_WORDS + w + 1] = l1;
        }
        __syncthreads();

        // prefetch Pa + neighbor Pc rows for layer-0 epilogue
        float2 pfa[4], pf0[4], pf1[4];
        {
            int gb = (node >> 11) * NN;
            int nbr0 = gb + s_idx[r_lo];
            int nbr1 = gb + s_idx[r_hi];
#pragma unroll
            for (int nt = 0; nt < 4; ++nt) {
                int c = n0 + nt * 8 + t * 2;
                pfa[nt] = *(const float2*)(g_Pa + (size_t)node * CC + c);
                pf0[nt] = *(const float2*)(g_Pc + (size_t)nbr0 * CC + c);
                pf1[nt] = *(const float2*)(g_Pc + (size_t)nbr1 * CC + c);
            }
        }

        for (int layer = 0; layer < 3; ++layer) {
            if (layer == 2) {
                int nn = node + gridDim.x;
                if (nn < BN) {
                    const float4* he4 = (const float4*)(h_E + (size_t)nn * (KK * CC));
#pragma unroll
                    for (int i = 0; i < 4; ++i) r_he[i] = he4[tid + 384 * i];
                }
            }

            // three independent accumulator banks — no back-to-back RAW on HMMA
            float acc_h[4][4], acc_l[4][4], acc_m[4][4];
#pragma unroll
            for (int nt = 0; nt < 4; ++nt)
#pragma unroll
                for (int j = 0; j < 4; ++j) {
                    acc_h[nt][j] = 0.0f; acc_l[nt][j] = 0.0f; acc_m[nt][j] = 0.0f;
                }

            const uint2* WH = (const uint2*)(smW + (layer * 2) * 8192);
            const uint2* WL = WH + 4096;
#pragma unroll
            for (int ks = 0; ks < 8; ++ks) {
                uint32_t ahi[4], alo[4];
                int aw = r_lo * A_STRIDE_W + ks * 8 + t;
                int aw2 = r_hi * A_STRIDE_W + ks * 8 + t;
                ahi[0] = smA[aw];        ahi[1] = smA[aw2];
                ahi[2] = smA[aw + 4];    ahi[3] = smA[aw2 + 4];
                alo[0] = smA[A_WORDS + aw];     alo[1] = smA[A_WORDS + aw2];
                alo[2] = smA[A_WORDS + aw + 4]; alo[3] = smA[A_WORDS + aw2 + 4];
#pragma unroll
                for (int nt = 0; nt < 4; ++nt) {
                    int chunk = (ntg0 + nt) * 8 + ks;
                    uint2 bh = WH[chunk * 32 + lane];
                    uint2 bl = WL[chunk * 32 + lane];
                    mma16816(acc_h[nt], ahi, bh.x, bh.y);
                    mma16816(acc_l[nt], alo, bh.x, bh.y);
                    mma16816(acc_m[nt], ahi, bl.x, bl.y);
                }
            }
            // combine banks
            float acc[4][4];
#pragma unroll
            for (int nt = 0; nt < 4; ++nt)
#pragma unroll
                for (int j = 0; j < 4; ++j)
                    acc[nt][j] = acc_h[nt][j] + acc_l[nt][j] + acc_m[nt][j];
            __syncthreads();

            if (layer < 2) {
#pragma unroll
                for (int nt = 0; nt < 4; ++nt) {
                    int c = n0 + nt * 8 + t * 2;
                    float a0, a1, b0, b1;
                    if (layer == 0) {
                        a0 = pfa[nt].x + pf0[nt].x; a1 = pfa[nt].y + pf0[nt].y;
                        b0 = pfa[nt].x + pf1[nt].x; b1 = pfa[nt].y + pf1[nt].y;
                    } else {
                        a0 = s_b2[c]; a1 = s_b2[c + 1];
                        b0 = a0; b1 = a1;
                    }
                    float xl0 = gelu_f(acc[nt][0] + a0);
                    float xl1 = gelu_f(acc[nt][1] + a1);
                    float xh0 = gelu_f(acc[nt][2] + b0);
                    float xh1 = gelu_f(acc[nt][3] + b1);
                    uint32_t hh, ll;
                    int w0 = r_lo * A_STRIDE_W + c / 2;
                    int w1 = r_hi * A_STRIDE_W + c / 2;
                    split_pack(xl0, xl1, hh, ll);
                    smA[w0] = hh; smA[A_WORDS + w0] = ll;
                    split_pack(xh0, xh1, hh, ll);
                    smA[w1] = hh; smA[A_WORDS + w1] = ll;
                }
                __syncthreads();
            } else if (!EDGE_OUT) {
                float mlo = s_mask[r_lo], mhi = s_mask[r_hi];
#pragma unroll
                for (int nt = 0; nt < 4; ++nt) {
                    int c = n0 + nt * 8 + t * 2;
                    float2 v0, v1;
                    v0.x = mlo * (acc[nt][0] + s_b3[c]);
                    v0.y = mlo * (acc[nt][1] + s_b3[c + 1]);
                    v1.x = mhi * (acc[nt][2] + s_b3[c]);
                    v1.y = mhi * (acc[nt][3] + s_b3[c + 1]);
                    *(float2*)(Fs + r_lo * 132 + c) = v0;
                    *(float2*)(Fs + r_hi * 132 + c) = v1;
                }
                __syncthreads();
                if (tid < CC) {
                    float s = 0.0f;
#pragma unroll
                    for (int r = 0; r < KK; ++r) s += Fs[r * 132 + tid];
                    g_dh[(size_t)node * CC + tid] = s;
                }
            } else {
                const float* he = h_E + (size_t)node * (KK * CC);
                float v[4][4];
                float sl = 0.0f, ql = 0.0f, sh = 0.0f, qh = 0.0f;
#pragma unroll
                for (int nt = 0; nt < 4; ++nt) {
                    int c = n0 + nt * 8 + t * 2;
                    float2 e0 = *(const float2*)(he + r_lo * CC + c);
                    float2 e1 = *(const float2*)(he + r_hi * CC + c);
                    v[nt][0] = acc[nt][0] + s_b3[c] + e0.x;
                    v[nt][1] = acc[nt][1] + s_b3[c + 1] + e0.y;
                    v[nt][2] = acc[nt][2] + s_b3[c] + e1.x;
                    v[nt][3] = acc[nt][3] + s_b3[c + 1] + e1.y;
                    sl += v[nt][0] + v[nt][1]; ql += v[nt][0] * v[nt][0] + v[nt][1] * v[nt][1];
                    sh += v[nt][2] + v[nt][3]; qh += v[nt][2] * v[nt][2] + v[nt][3] * v[nt][3];
                }
#pragma unroll
                for (int off = 1; off <= 2; off <<= 1) {
                    sl += __shfl_xor_sync(0xffffffffu, sl, off);
                    ql += __shfl_xor_sync(0xffffffffu, ql, off);
                    sh += __shfl_xor_sync(0xffffffffu, sh, off);
                    qh += __shfl_xor_sync(0xffffffffu, qh, off);
                }
                if (t == 0) {
                    s_red[r_lo][nchunk][0] = sl; s_red[r_lo][nchunk][1] = ql;
                    s_red[r_hi][nchunk][0] = sh; s_red[r_hi][nchunk][1] = qh;
                }
                __syncthreads();
                float S0 = 0, Q0 = 0, S1 = 0, Q1 = 0;
#pragma unroll
                for (int w = 0; w < 4; ++w) {
                    S0 += s_red[r_lo][w][0]; Q0 += s_red[r_lo][w][1];
                    S1 += s_red[r_hi][w][0]; Q1 += s_red[r_hi][w][1];
                }
                float m0f = S0 * (1.0f / 128.0f);
                float rs0 = rsqrtf(Q0 * (1.0f / 128.0f) - m0f * m0f + EPSLN);
                float m1f = S1 * (1.0f / 128.0f);
                float rs1 = rsqrtf(Q1 * (1.0f / 128.0f) - m1f * m1f + EPSLN);
                float* op = outp + (size_t)node * (KK * CC);
#pragma unroll
                for (int nt = 0; nt < 4; ++nt) {
                    int c = n0 + nt * 8 + t * 2;
                    float2 o0, o1;
                    o0.x = s_g3[c] * (v[nt][0] - m0f) * rs0 + s_bl[c];
                    o0.y = s_g3[c + 1] * (v[nt][1] - m0f) * rs0 + s_bl[c + 1];
                    o1.x = s_g3[c] * (v[nt][2] - m1f) * rs1 + s_bl[c];
                    o1.y = s_g3[c + 1] * (v[nt][3] - m1f) * rs1 + s_bl[c + 1];
                    *(float2*)(op + r_lo * CC + c) = o0;
                    *(float2*)(op + r_hi * CC + c) = o1;
                }
            }
        }
    }
}

// ---------------------------------------------------------------------------
// Scalar node kernels — Round-6 proven versions (32 nodes/block).
// ---------------------------------------------------------------------------
template <int R>
__device__ __forceinline__ void mm_tile(float acc[R][4], const float* Xs, int xstride4,
                                        const float* Ws, int r0, int lane) {
    const float4* X4 = (const float4*)Xs;
    const float4* W4 = (const float4*)Ws;
#pragma unroll 4
    for (int kq = 0; kq < 32; ++kq) {
        float4 w0 = W4[(4 * kq + 0) * 32 + lane];
        float4 w1 = W4[(4 * kq + 1) * 32 + lane];
        float4 w2 = W4[(4 * kq + 2) * 32 + lane];
        float4 w3 = W4[(4 * kq + 3) * 32 + lane];
#pragma unroll
        for (int i = 0; i < R; ++i) {
            float4 x = X4[(r0 + i) * xstride4 + kq];
            acc[i][0] = fmaf(x.x, w0.x, acc[i][0]); acc[i][1] = fmaf(x.x, w0.y, acc[i][1]);
            acc[i][2] = fmaf(x.x, w0.z, acc[i][2]); acc[i][3] = fmaf(x.x, w0.w, acc[i][3]);
            acc[i][0] = fmaf(x.y, w1.x, acc[i][0]); acc[i][1] = fmaf(x.y, w1.y, acc[i][1]);
            acc[i][2] = fmaf(x.y, w1.z, acc[i][2]); acc[i][3] = fmaf(x.y, w1.w, acc[i][3]);
            acc[i][0] = fmaf(x.z, w2.x, acc[i][0]); acc[i][1] = fmaf(x.z, w2.y, acc[i][1]);
            acc[i][2] = fmaf(x.z, w2.z, acc[i][2]); acc[i][3] = fmaf(x.z, w2.w, acc[i][3]);
            acc[i][0] = fmaf(x.w, w3.x, acc[i][0]); acc[i][1] = fmaf(x.w, w3.y, acc[i][1]);
            acc[i][2] = fmaf(x.w, w3.z, acc[i][2]); acc[i][3] = fmaf(x.w, w3.w, acc[i][3]);
        }
    }
}

__global__ void __launch_bounds__(512) nodepre_kernel(
    const float* __restrict__ hV, const float* __restrict__ W1,
    const float* __restrict__ b1) {
    extern __shared__ float sm[];
    float* Vs = sm;
    float* Ws = sm + 4096;
    int tid = threadIdx.x, lane = tid & 31, warp = tid >> 5;
    size_t base = (size_t)blockIdx.x * 32 * CC;
    {
        const float4* src = (const float4*)(hV + base);
        float4* dst = (float4*)Vs;
#pragma unroll
        for (int e = 0; e < 2; ++e) dst[tid + 512 * e] = src[tid + 512 * e];
    }
    {
        const float4* src = (const float4*)W1;
        float4* dst = (float4*)Ws;
#pragma unroll
        for (int e = 0; e < 8; ++e) dst[tid + 512 * e] = src[tid + 512 * e];
    }
    __syncthreads();
    int r0 = warp * 2, c0 = lane * 4;
    float acc[2][4];
#pragma unroll
    for (int j = 0; j < 4; ++j) { float b = b1[c0 + j]; acc[0][j] = b; acc[1][j] = b; }
    mm_tile<2>(acc, Vs, 32, Ws, r0, lane);
#pragma unroll
    for (int i = 0; i < 2; ++i)
#pragma unroll
        for (int j = 0; j < 4; ++j)
            g_Pa[base + (size_t)(r0 + i) * CC + c0 + j] = acc[i][j];
    __syncthreads();
    {
        const float4* src = (const float4*)(W1 + 2 * CC * CC);
        float4* dst = (float4*)Ws;
#pragma unroll
        for (int e = 0; e < 8; ++e) dst[tid + 512 * e] = src[tid + 512 * e];
    }
    __syncthreads();
#pragma unroll
    for (int i = 0; i < 2; ++i)
#pragma unroll
        for (int j = 0; j < 4; ++j) acc[i][j] = 0.0f;
    mm_tile<2>(acc, Vs, 32, Ws, r0, lane);
#pragma unroll
    for (int i = 0; i < 2; ++i)
#pragma unroll
        for (int j = 0; j < 4; ++j)
            g_Pc[base + (size_t)(r0 + i) * CC + c0 + j] = acc[i][j];
}

__global__ void __launch_bounds__(512) ffn_kernel(
    const float* __restrict__ hV,
    const float* __restrict__ Win_w, const float* __restrict__ Win_b,
    const float* __restrict__ Wout_w, const float* __restrict__ Wout_b,
    const float* __restrict__ g1, const float* __restrict__ b1,
    const float* __restrict__ g2, const float* __restrict__ b2,
    const float* __restrict__ mask_V, float* __restrict__ out) {
    extern __shared__ float sm[];
    float* V1s = sm;
    float* Ts = sm + 4096;
    float* Ws = sm + 4096 + 16384;
    int tid = threadIdx.x, lane = tid & 31, warp = tid >> 5;
    size_t base = (size_t)blockIdx.x * 32 * CC;
    int c0 = lane * 4, r0 = warp * 2;
#pragma unroll
    for (int i = 0; i < 2; ++i) {
        int r = r0 + i;
        float4 xv = *(const float4*)(hV + base + (size_t)r * CC + c0);
        float4 dv = *(const float4*)(&g_dh[base + (size_t)r * CC + c0]);
        float x0 = xv.x + dv.x * INV_SCALE, x1 = xv.y + dv.y * INV_SCALE;
        float x2 = xv.z + dv.z * INV_SCALE, x3 = xv.w + dv.w * INV_SCALE;
        float s = x0 + x1 + x2 + x3;
        float q = x0 * x0 + x1 * x1 + x2 * x2 + x3 * x3;
#pragma unroll
        for (int off = 16; off; off >>= 1) {
            s += __shfl_xor_sync(0xffffffffu, s, off);
            q += __shfl_xor_sync(0xffffffffu, q, off);
        }
        float mean = s * (1.0f / 128.0f);
        float var = q * (1.0f / 128.0f) - mean * mean;
        float rs = rsqrtf(var + EPSLN);
        float4 o;
        o.x = g1[c0 + 0] * (x0 - mean) * rs + b1[c0 + 0];
        o.y = g1[c0 + 1] * (x1 - mean) * rs + b1[c0 + 1];
        o.z = g1[c0 + 2] * (x2 - mean) * rs + b1[c0 + 2];
        o.w = g1[c0 + 3] * (x3 - mean) * rs + b1[c0 + 3];
        *(float4*)(V1s + r * CC + c0) = o;
    }
    __syncthreads();
    for (int ct = 0; ct < 4; ++ct) {
        if (ct) __syncthreads();
        for (int e = tid; e < 4096; e += 512) {
            int k = e >> 5, cq = e & 31;
            ((float4*)Ws)[e] = ((const float4*)Win_w)[k * 128 + ct * 32 + cq];
        }
        __syncthreads();
        float acc[2][4];
#pragma unroll
        for (int j = 0; j < 4; ++j) {
            float b = Win_b[ct * 128 + c0 + j];
            acc[0][j] = b; acc[1][j] = b;
        }
        mm_tile<2>(acc, V1s, 32, Ws, r0, lane);
#pragma unroll
        for (int i = 0; i < 2; ++i)
#pragma unroll
            for (int j = 0; j < 4; ++j)
                Ts[(r0 + i) * FFD + ct * 128 + c0 + j] = gelu_f(acc[i][j]);
    }
    __syncthreads();
    float acc[2][4];
#pragma unroll
    for (int j = 0; j < 4; ++j) {
        float b = Wout_b[c0 + j];
        acc[0][j] = b; acc[1][j] = b;
    }
    for (int kt = 0; kt < 4; ++kt) {
        if (kt) __syncthreads();
        for (int e = tid; e < 4096; e += 512)
            ((float4*)Ws)[e] = ((const float4*)Wout_w)[kt * 4096 + e];
        __syncthreads();
        mm_tile<2>(acc, Ts + kt * 128, 128, Ws, r0, lane);
    }
#pragma unroll
    for (int i = 0; i < 2; ++i) {
        int r = r0 + i;
        float v0 = V1s[r * CC + c0 + 0] + acc[i][0];
        float v1 = V1s[r * CC + c0 + 1] + acc[i][1];
        float v2 = V1s[r * CC + c0 + 2] + acc[i][2];
        float v3 = V1s[r * CC + c0 + 3] + acc[i][3];
        float s = v0 + v1 + v2 + v3;
        float q = v0 * v0 + v1 * v1 + v2 * v2 + v3 * v3;
#pragma unroll
        for (int off = 16; off; off >>= 1) {
            s += __shfl_xor_sync(0xffffffffu, s, off);
            q += __shfl_xor_sync(0xffffffffu, q, off);
        }
        float mean = s * (1.0f / 128.0f);
        float var = q * (1.0f / 128.0f) - mean * mean;
        float rs = rsqrtf(var + EPSLN);
        float mv = mask_V[blockIdx.x * 32 + r];
        float4 o;
        o.x = (g2[c0 + 0] * (v0 - mean) * rs + b2[c0 + 0]) * mv;
        o.y = (g2[c0 + 1] * (v1 - mean) * rs + b2[c0 + 1]) * mv;
        o.z = (g2[c0 + 2] * (v2 - mean) * rs + b2[c0 + 2]) * mv;
        o.w = (g2[c0 + 3] * (v3 - mean) * rs + b2[c0 + 3]) * mv;
        *(float4*)(out + base + (size_t)r * CC + c0) = o;
    }
}

// ---------------------------------------------------------------------------
extern "C" void kernel_launch(void* const* d_in, const int* in_sizes, int n_in,
                              void* d_out, int out_size) {
    const float* h_V = (const float*)d_in[0];
    const float* h_E = (const float*)d_in[1];
    const int* E_idx = (const int*)d_in[2];
    const float* mask_V = (const float*)d_in[3];
    const float* mask_attend = (const float*)d_in[4];
    const float* W1_w = (const float*)d_in[5];
    const float* W1_b = (const float*)d_in[6];
    const float* W2_w = (const float*)d_in[7];
    const float* W2_b = (const float*)d_in[8];
    const float* W3_w = (const float*)d_in[9];
    const float* W3_b = (const float*)d_in[10];
    const float* W11_w = (const float*)d_in[11];
    const float* W11_b = (const float*)d_in[12];
    const float* W12_w = (const float*)d_in[13];
    const float* W12_b = (const float*)d_in[14];
    const float* W13_w = (const float*)d_in[15];
    const float* W13_b = (const float*)d_in[16];
    const float* Win_w = (const float*)d_in[17];
    const float* Win_b = (const float*)d_in[18];
    const float* Wout_w = (const float*)d_in[19];
    const float* Wout_b = (const float*)d_in[20];
    const float* g1 = (const float*)d_in[21];
    const float* b1 = (const float*)d_in[22];
    const float* g2 = (const float*)d_in[23];
    const float* b2 = (const float*)d_in[24];
    const float* g3 = (const float*)d_in[25];
    const float* b3 = (const float*)d_in[26];

    float* out_hV = (float*)d_out;
    float* out_hE = out_hV + (size_t)BN * CC;

    const int SMEM_PRE = (4096 + 16384) * 4;          // 80 KB
    const int SMEM_FFN = (4096 + 16384 + 16384) * 4;  // 144 KB

    cudaFuncSetAttribute(nodepre_kernel, cudaFuncAttributeMaxDynamicSharedMemorySize, SMEM_PRE);
    cudaFuncSetAttribute(ffn_kernel, cudaFuncAttributeMaxDynamicSharedMemorySize, SMEM_FFN);
    cudaFuncSetAttribute(edge_mma_kernel<false>, cudaFuncAttributeMaxDynamicSharedMemorySize, SMEM_EDGE_DYN);
    cudaFuncSetAttribute(edge_mma_kernel<true>, cudaFuncAttributeMaxDynamicSharedMemorySize, SMEM_EDGE_DYN);

    prep_weights<<<12, 256>>>(W1_w + CC * CC, W2_w, W3_w, W11_w + CC * CC, W12_w, W13_w);
    nodepre_kernel<<<BN / 32, 512, SMEM_PRE>>>(h_V, W1_w, W1_b);
    edge_mma_kernel<false><<<148, 384, SMEM_EDGE_DYN>>>(h_E, E_idx, mask_attend, 0,
                                                        W2_b, W3_b, g3, b3, out_hE);
    ffn_kernel<<<BN / 32, 512, SMEM_FFN>>>(h_V, Win_w, Win_b, Wout_w, Wout_b,
                                           g1, b1, g2, b2, mask_V, out_hV);
    nodepre_kernel<<<BN / 32, 512, SMEM_PRE>>>(out_hV, W11_w, W11_b);
    edge_mma_kernel<true><<<148, 384, SMEM_EDGE_DYN>>>(h_E, E_idx, mask_attend, 1,
                                                       W12_b, W13_b, g3, b3, out_hE);
}

// round 10
// speedup vs baseline: 1.2072x; 1.1567x over previous
#include <cuda_runtime.h>
#include <cuda_fp16.h>
#include <math.h>
#include <stdint.h>

#define BB 2
#define NN 2048
#define KK 48
#define CC 128
#define FFD 512
#define BN (BB * NN)
#define EPSLN 1e-5f
#define INV_SCALE (1.0f / 30.0f)

// ---------------- device scratch ----------------
__device__ float g_Pa[BN * CC];   // h_V @ W1a + b1
__device__ float g_Pc[BN * CC];   // h_V @ W1c
__device__ float g_dh[BN * CC];   // masked message sum
// 6 weight images (2 sets x 3 layers), 128x128 fp16, HMMA B-fragment order
__device__ __half g_Wimg[6 * 16384];

__device__ __forceinline__ float gelu_f(float x) {
    return 0.5f * x * (1.0f + erff(x * 0.70710678118654752f));
}
// fp16 exact-residual split: (a,b) -> hi half2, lo half2 (x = hi + lo, err ~2^-22)
__device__ __forceinline__ void split_pack(float a, float b, uint32_t& hi, uint32_t& lo) {
    __half ah = __float2half_rn(a);
    __half bh = __float2half_rn(b);
    __half2 hp; hp.x = ah; hp.y = bh;
    __half2 lp;
    lp.x = __float2half_rn(a - __half2float(ah));
    lp.y = __float2half_rn(b - __half2float(bh));
    hi = *reinterpret_cast<uint32_t*>(&hp);
    lo = *reinterpret_cast<uint32_t*>(&lp);
}
__device__ __forceinline__ void mma16816(float c[4], const uint32_t a[4],
                                         uint32_t b0, uint32_t b1) {
    asm volatile(
        "mma.sync.aligned.m16n8k16.row.col.f32.f16.f16.f32 "
        "{%0,%1,%2,%3}, {%4,%5,%6,%7}, {%8,%9}, {%0,%1,%2,%3};"
        : "+f"(c[0]), "+f"(c[1]), "+f"(c[2]), "+f"(c[3])
        : "r"(a[0]), "r"(a[1]), "r"(a[2]), "r"(a[3]), "r"(b0), "r"(b1));
}

// ---------------------------------------------------------------------------
// Weight prep: 6 fp16 images in HMMA B-fragment order (layout proven in bf16).
// ---------------------------------------------------------------------------
__global__ void prep_weights(const float* __restrict__ A0, const float* __restrict__ A1,
                             const float* __restrict__ A2, const float* __restrict__ B0,
                             const float* __restrict__ B1, const float* __restrict__ B2) {
    const float* srcs[6] = {A0, A1, A2, B0, B1, B2};
    int img = blockIdx.x;                      // set*3 + layer
    const float* s = srcs[img];
    __half* dst = g_Wimg + (size_t)img * 16384;
    for (int e = threadIdx.x; e < 16384; e += blockDim.x) {
        int k = e >> 7, n = e & 127;
        int kk = k & 15;
        int t = (kk & 7) >> 1, hi8 = kk >> 3, idx = kk & 1;
        int lane = (n & 7) * 4 + t;
        int chunk = (n >> 3) * 8 + (k >> 4);
        dst[chunk * 128 + lane * 4 + hi8 * 2 + idx] = __float2half_rn(s[e]);
    }
}

// ---------------------------------------------------------------------------
// HMMA edge MLP — fp16 2-split: hi@W + lo@W (weights single fp16).
// ---------------------------------------------------------------------------
#define A_STRIDE_W 68
#define A_WORDS (KK * A_STRIDE_W)
#define SMEM_W_BYTES 98304                      // 3 images x 32 KB
#define SMEM_EDGE_DYN (SMEM_W_BYTES + 2 * A_WORDS * 4)

template <bool EDGE_OUT>
__global__ void __launch_bounds__(384, 1) edge_mma_kernel(
    const float* __restrict__ h_E, const int* __restrict__ E_idx,
    const float* __restrict__ mask_attend, int wset,
    const float* __restrict__ b2v, const float* __restrict__ b3v,
    const float* __restrict__ g3v, const float* __restrict__ b3ln,
    float* __restrict__ outp) {
    extern __shared__ uint32_t smem[];
    uint32_t* smW = smem;
    uint32_t* smA = smem + (SMEM_W_BYTES / 4);
    float* Fs = (float*)smA;

    __shared__ int s_idx[KK];
    __shared__ float s_mask[KK];
    __shared__ float s_b2[CC], s_b3[CC], s_g3[CC], s_bl[CC];
    __shared__ float s_red[KK][4][2];

    const int tid = threadIdx.x, lane = tid & 31, wid = tid >> 5;
    const int g = lane >> 2, t = lane & 3;
    const int mtile = wid >> 2, nchunk = wid & 3;
    const int m0 = mtile * 16, n0 = nchunk * 32;
    const int ntg0 = nchunk * 4;

    {   // 96KB weight copy once per block
        const float4* src = (const float4*)(g_Wimg + (size_t)wset * 3 * 16384);
        float4* dst = (float4*)smW;
        for (int i = tid; i < 6144; i += 384) dst[i] = src[i];
    }
    if (tid < CC) {
        s_b2[tid] = b2v[tid];
        s_b3[tid] = b3v[tid];
        if (EDGE_OUT) { s_g3[tid] = g3v[tid]; s_bl[tid] = b3ln[tid]; }
    }

    const int r_lo = m0 + g, r_hi = m0 + g + 8;

    // prefetch first node's h_E tile
    float4 r_he[4];
    int node = blockIdx.x;
    if (node < BN) {
        const float4* he4 = (const float4*)(h_E + (size_t)node * (KK * CC));
#pragma unroll
        for (int i = 0; i < 4; ++i) r_he[i] = he4[tid + 384 * i];
    }

    for (; node < BN; node += gridDim.x) {
        __syncthreads();

        if (tid < KK) {
            s_idx[tid] = E_idx[node * KK + tid];
            s_mask[tid] = mask_attend[node * KK + tid];
        }
#pragma unroll
        for (int i = 0; i < 4; ++i) {
            int idx4 = tid + 384 * i;
            float4 v = r_he[i];
            int row = idx4 >> 5, colw = (idx4 & 31) * 2;
            uint32_t h0, l0, h1, l1;
            split_pack(v.x, v.y, h0, l0);
            split_pack(v.z, v.w, h1, l1);
            int w = row * A_STRIDE_W + colw;
            smA[w] = h0; smA[w + 1] = h1;
            smA[A_WORDS + w] = l0; smA[A_WORDS + w + 1] = l1;
        }
        __syncthreads();

        // prefetch Pa + neighbor Pc rows for layer-0 epilogue
        float2 pfa[4], pf0[4], pf1[4];
        {
            int gb = (node >> 11) * NN;
            int nbr0 = gb + s_idx[r_lo];
            int nbr1 = gb + s_idx[r_hi];
#pragma unroll
            for (int nt = 0; nt < 4; ++nt) {
                int c = n0 + nt * 8 + t * 2;
                pfa[nt] = *(const float2*)(g_Pa + (size_t)node * CC + c);
                pf0[nt] = *(const float2*)(g_Pc + (size_t)nbr0 * CC + c);
                pf1[nt] = *(const float2*)(g_Pc + (size_t)nbr1 * CC + c);
            }
        }

        for (int layer = 0; layer < 3; ++layer) {
            if (layer == 2) {
                int nn = node + gridDim.x;
                if (nn < BN) {
                    const float4* he4 = (const float4*)(h_E + (size_t)nn * (KK * CC));
#pragma unroll
                    for (int i = 0; i < 4; ++i) r_he[i] = he4[tid + 384 * i];
                }
            }

            // two accumulator banks (hi-part / lo-part) — no back-to-back RAW
            float acc_h[4][4], acc_l[4][4];
#pragma unroll
            for (int nt = 0; nt < 4; ++nt)
#pragma unroll
                for (int j = 0; j < 4; ++j) { acc_h[nt][j] = 0.0f; acc_l[nt][j] = 0.0f; }

            const uint2* WH = (const uint2*)smW + layer * 4096;
#pragma unroll
            for (int ks = 0; ks < 8; ++ks) {
                uint32_t ahi[4], alo[4];
                int aw = r_lo * A_STRIDE_W + ks * 8 + t;
                int aw2 = r_hi * A_STRIDE_W + ks * 8 + t;
                ahi[0] = smA[aw];        ahi[1] = smA[aw2];
                ahi[2] = smA[aw + 4];    ahi[3] = smA[aw2 + 4];
                alo[0] = smA[A_WORDS + aw];     alo[1] = smA[A_WORDS + aw2];
                alo[2] = smA[A_WORDS + aw + 4]; alo[3] = smA[A_WORDS + aw2 + 4];
#pragma unroll
                for (int nt = 0; nt < 4; ++nt) {
                    int chunk = (ntg0 + nt) * 8 + ks;
                    uint2 bh = WH[chunk * 32 + lane];
                    mma16816(acc_h[nt], ahi, bh.x, bh.y);
                    mma16816(acc_l[nt], alo, bh.x, bh.y);
                }
            }
            float acc[4][4];
#pragma unroll
            for (int nt = 0; nt < 4; ++nt)
#pragma unroll
                for (int j = 0; j < 4; ++j) acc[nt][j] = acc_h[nt][j] + acc_l[nt][j];
            __syncthreads();

            if (layer < 2) {
#pragma unroll
                for (int nt = 0; nt < 4; ++nt) {
                    int c = n0 + nt * 8 + t * 2;
                    float a0, a1, b0, b1;
                    if (layer == 0) {
                        a0 = pfa[nt].x + pf0[nt].x; a1 = pfa[nt].y + pf0[nt].y;
                        b0 = pfa[nt].x + pf1[nt].x; b1 = pfa[nt].y + pf1[nt].y;
                    } else {
                        a0 = s_b2[c]; a1 = s_b2[c + 1];
                        b0 = a0; b1 = a1;
                    }
                    float xl0 = gelu_f(acc[nt][0] + a0);
                    float xl1 = gelu_f(acc[nt][1] + a1);
                    float xh0 = gelu_f(acc[nt][2] + b0);
                    float xh1 = gelu_f(acc[nt][3] + b1);
                    uint32_t hh, ll;
                    int w0 = r_lo * A_STRIDE_W + c / 2;
                    int w1 = r_hi * A_STRIDE_W + c / 2;
                    split_pack(xl0, xl1, hh, ll);
                    smA[w0] = hh; smA[A_WORDS + w0] = ll;
                    split_pack(xh0, xh1, hh, ll);
                    smA[w1] = hh; smA[A_WORDS + w1] = ll;
                }
                __syncthreads();
            } else if (!EDGE_OUT) {
                float mlo = s_mask[r_lo], mhi = s_mask[r_hi];
#pragma unroll
                for (int nt = 0; nt < 4; ++nt) {
                    int c = n0 + nt * 8 + t * 2;
                    float2 v0, v1;
                    v0.x = mlo * (acc[nt][0] + s_b3[c]);
                    v0.y = mlo * (acc[nt][1] + s_b3[c + 1]);
                    v1.x = mhi * (acc[nt][2] + s_b3[c]);
                    v1.y = mhi * (acc[nt][3] + s_b3[c + 1]);
                    *(float2*)(Fs + r_lo * 132 + c) = v0;
                    *(float2*)(Fs + r_hi * 132 + c) = v1;
                }
                __syncthreads();
                if (tid < CC) {
                    float s = 0.0f;
#pragma unroll
                    for (int r = 0; r < KK; ++r) s += Fs[r * 132 + tid];
                    g_dh[(size_t)node * CC + tid] = s;
                }
            } else {
                const float* he = h_E + (size_t)node * (KK * CC);
                float v[4][4];
                float sl = 0.0f, ql = 0.0f, sh = 0.0f, qh = 0.0f;
#pragma unroll
                for (int nt = 0; nt < 4; ++nt) {
                    int c = n0 + nt * 8 + t * 2;
                    float2 e0 = *(const float2*)(he + r_lo * CC + c);
                    float2 e1 = *(const float2*)(he + r_hi * CC + c);
                    v[nt][0] = acc[nt][0] + s_b3[c] + e0.x;
                    v[nt][1] = acc[nt][1] + s_b3[c + 1] + e0.y;
                    v[nt][2] = acc[nt][2] + s_b3[c] + e1.x;
                    v[nt][3] = acc[nt][3] + s_b3[c + 1] + e1.y;
                    sl += v[nt][0] + v[nt][1]; ql += v[nt][0] * v[nt][0] + v[nt][1] * v[nt][1];
                    sh += v[nt][2] + v[nt][3]; qh += v[nt][2] * v[nt][2] + v[nt][3] * v[nt][3];
                }
#pragma unroll
                for (int off = 1; off <= 2; off <<= 1) {
                    sl += __shfl_xor_sync(0xffffffffu, sl, off);
                    ql += __shfl_xor_sync(0xffffffffu, ql, off);
                    sh += __shfl_xor_sync(0xffffffffu, sh, off);
                    qh += __shfl_xor_sync(0xffffffffu, qh, off);
                }
                if (t == 0) {
                    s_red[r_lo][nchunk][0] = sl; s_red[r_lo][nchunk][1] = ql;
                    s_red[r_hi][nchunk][0] = sh; s_red[r_hi][nchunk][1] = qh;
                }
                __syncthreads();
                float S0 = 0, Q0 = 0, S1 = 0, Q1 = 0;
#pragma unroll
                for (int w = 0; w < 4; ++w) {
                    S0 += s_red[r_lo][w][0]; Q0 += s_red[r_lo][w][1];
                    S1 += s_red[r_hi][w][0]; Q1 += s_red[r_hi][w][1];
                }
                float m0f = S0 * (1.0f / 128.0f);
                float rs0 = rsqrtf(Q0 * (1.0f / 128.0f) - m0f * m0f + EPSLN);
                float m1f = S1 * (1.0f / 128.0f);
                float rs1 = rsqrtf(Q1 * (1.0f / 128.0f) - m1f * m1f + EPSLN);
                float* op = outp + (size_t)node * (KK * CC);
#pragma unroll
                for (int nt = 0; nt < 4; ++nt) {
                    int c = n0 + nt * 8 + t * 2;
                    float2 o0, o1;
                    o0.x = s_g3[c] * (v[nt][0] - m0f) * rs0 + s_bl[c];
                    o0.y = s_g3[c + 1] * (v[nt][1] - m0f) * rs0 + s_bl[c + 1];
                    o1.x = s_g3[c] * (v[nt][2] - m1f) * rs1 + s_bl[c];
                    o1.y = s_g3[c + 1] * (v[nt][3] - m1f) * rs1 + s_bl[c + 1];
                    *(float2*)(op + r_lo * CC + c) = o0;
                    *(float2*)(op + r_hi * CC + c) = o1;
                }
            }
        }
    }
}

// ---------------------------------------------------------------------------
// Scalar node kernels — proven Round-6 versions (32 nodes/block).
// ---------------------------------------------------------------------------
template <int R>
__device__ __forceinline__ void mm_tile(float acc[R][4], const float* Xs, int xstride4,
                                        const float* Ws, int r0, int lane) {
    const float4* X4 = (const float4*)Xs;
    const float4* W4 = (const float4*)Ws;
#pragma unroll 4
    for (int kq = 0; kq < 32; ++kq) {
        float4 w0 = W4[(4 * kq + 0) * 32 + lane];
        float4 w1 = W4[(4 * kq + 1) * 32 + lane];
        float4 w2 = W4[(4 * kq + 2) * 32 + lane];
        float4 w3 = W4[(4 * kq + 3) * 32 + lane];
#pragma unroll
        for (int i = 0; i < R; ++i) {
            float4 x = X4[(r0 + i) * xstride4 + kq];
            acc[i][0] = fmaf(x.x, w0.x, acc[i][0]); acc[i][1] = fmaf(x.x, w0.y, acc[i][1]);
            acc[i][2] = fmaf(x.x, w0.z, acc[i][2]); acc[i][3] = fmaf(x.x, w0.w, acc[i][3]);
            acc[i][0] = fmaf(x.y, w1.x, acc[i][0]); acc[i][1] = fmaf(x.y, w1.y, acc[i][1]);
            acc[i][2] = fmaf(x.y, w1.z, acc[i][2]); acc[i][3] = fmaf(x.y, w1.w, acc[i][3]);
            acc[i][0] = fmaf(x.z, w2.x, acc[i][0]); acc[i][1] = fmaf(x.z, w2.y, acc[i][1]);
            acc[i][2] = fmaf(x.z, w2.z, acc[i][2]); acc[i][3] = fmaf(x.z, w2.w, acc[i][3]);
            acc[i][0] = fmaf(x.w, w3.x, acc[i][0]); acc[i][1] = fmaf(x.w, w3.y, acc[i][1]);
            acc[i][2] = fmaf(x.w, w3.z, acc[i][2]); acc[i][3] = fmaf(x.w, w3.w, acc[i][3]);
        }
    }
}

__global__ void __launch_bounds__(512) nodepre_kernel(
    const float* __restrict__ hV, const float* __restrict__ W1,
    const float* __restrict__ b1) {
    extern __shared__ float sm[];
    float* Vs = sm;
    float* Ws = sm + 4096;
    int tid = threadIdx.x, lane = tid & 31, warp = tid >> 5;
    size_t base = (size_t)blockIdx.x * 32 * CC;
    {
        const float4* src = (const float4*)(hV + base);
        float4* dst = (float4*)Vs;
#pragma unroll
        for (int e = 0; e < 2; ++e) dst[tid + 512 * e] = src[tid + 512 * e];
    }
    {
        const float4* src = (const float4*)W1;
        float4* dst = (float4*)Ws;
#pragma unroll
        for (int e = 0; e < 8; ++e) dst[tid + 512 * e] = src[tid + 512 * e];
    }
    __syncthreads();
    int r0 = warp * 2, c0 = lane * 4;
    float acc[2][4];
#pragma unroll
    for (int j = 0; j < 4; ++j) { float b = b1[c0 + j]; acc[0][j] = b; acc[1][j] = b; }
    mm_tile<2>(acc, Vs, 32, Ws, r0, lane);
#pragma unroll
    for (int i = 0; i < 2; ++i)
#pragma unroll
        for (int j = 0; j < 4; ++j)
            g_Pa[base + (size_t)(r0 + i) * CC + c0 + j] = acc[i][j];
    __syncthreads();
    {
        const float4* src = (const float4*)(W1 + 2 * CC * CC);
        float4* dst = (float4*)Ws;
#pragma unroll
        for (int e = 0; e < 8; ++e) dst[tid + 512 * e] = src[tid + 512 * e];
    }
    __syncthreads();
#pragma unroll
    for (int i = 0; i < 2; ++i)
#pragma unroll
        for (int j = 0; j < 4; ++j) acc[i][j] = 0.0f;
    mm_tile<2>(acc, Vs, 32, Ws, r0, lane);
#pragma unroll
    for (int i = 0; i < 2; ++i)
#pragma unroll
        for (int j = 0; j < 4; ++j)
            g_Pc[base + (size_t)(r0 + i) * CC + c0 + j] = acc[i][j];
}

__global__ void __launch_bounds__(512) ffn_kernel(
    const float* __restrict__ hV,
    const float* __restrict__ Win_w, const float* __restrict__ Win_b,
    const float* __restrict__ Wout_w, const float* __restrict__ Wout_b,
    const float* __restrict__ g1, const float* __restrict__ b1,
    const float* __restrict__ g2, const float* __restrict__ b2,
    const float* __restrict__ mask_V, float* __restrict__ out) {
    extern __shared__ float sm[];
    float* V1s = sm;
    float* Ts = sm + 4096;
    float* Ws = sm + 4096 + 16384;
    int tid = threadIdx.x, lane = tid & 31, warp = tid >> 5;
    size_t base = (size_t)blockIdx.x * 32 * CC;
    int c0 = lane * 4, r0 = warp * 2;
#pragma unroll
    for (int i = 0; i < 2; ++i) {
        int r = r0 + i;
        float4 xv = *(const float4*)(hV + base + (size_t)r * CC + c0);
        float4 dv = *(const float4*)(&g_dh[base + (size_t)r * CC + c0]);
        float x0 = xv.x + dv.x * INV_SCALE, x1 = xv.y + dv.y * INV_SCALE;
        float x2 = xv.z + dv.z * INV_SCALE, x3 = xv.w + dv.w * INV_SCALE;
        float s = x0 + x1 + x2 + x3;
        float q = x0 * x0 + x1 * x1 + x2 * x2 + x3 * x3;
#pragma unroll
        for (int off = 16; off; off >>= 1) {
            s += __shfl_xor_sync(0xffffffffu, s, off);
            q += __shfl_xor_sync(0xffffffffu, q, off);
        }
        float mean = s * (1.0f / 128.0f);
        float var = q * (1.0f / 128.0f) - mean * mean;
        float rs = rsqrtf(var + EPSLN);
        float4 o;
        o.x = g1[c0 + 0] * (x0 - mean) * rs + b1[c0 + 0];
        o.y = g1[c0 + 1] * (x1 - mean) * rs + b1[c0 + 1];
        o.z = g1[c0 + 2] * (x2 - mean) * rs + b1[c0 + 2];
        o.w = g1[c0 + 3] * (x3 - mean) * rs + b1[c0 + 3];
        *(float4*)(V1s + r * CC + c0) = o;
    }
    __syncthreads();
    for (int ct = 0; ct < 4; ++ct) {
        if (ct) __syncthreads();
        for (int e = tid; e < 4096; e += 512) {
            int k = e >> 5, cq = e & 31;
            ((float4*)Ws)[e] = ((const float4*)Win_w)[k * 128 + ct * 32 + cq];
        }
        __syncthreads();
        float acc[2][4];
#pragma unroll
        for (int j = 0; j < 4; ++j) {
            float b = Win_b[ct * 128 + c0 + j];
            acc[0][j] = b; acc[1][j] = b;
        }
        mm_tile<2>(acc, V1s, 32, Ws, r0, lane);
#pragma unroll
        for (int i = 0; i < 2; ++i)
#pragma unroll
            for (int j = 0; j < 4; ++j)
                Ts[(r0 + i) * FFD + ct * 128 + c0 + j] = gelu_f(acc[i][j]);
    }
    __syncthreads();
    float acc[2][4];
#pragma unroll
    for (int j = 0; j < 4; ++j) {
        float b = Wout_b[c0 + j];
        acc[0][j] = b; acc[1][j] = b;
    }
    for (int kt = 0; kt < 4; ++kt) {
        if (kt) __syncthreads();
        for (int e = tid; e < 4096; e += 512)
            ((float4*)Ws)[e] = ((const float4*)Wout_w)[kt * 4096 + e];
        __syncthreads();
        mm_tile<2>(acc, Ts + kt * 128, 128, Ws, r0, lane);
    }
#pragma unroll
    for (int i = 0; i < 2; ++i) {
        int r = r0 + i;
        float v0 = V1s[r * CC + c0 + 0] + acc[i][0];
        float v1 = V1s[r * CC + c0 + 1] + acc[i][1];
        float v2 = V1s[r * CC + c0 + 2] + acc[i][2];
        float v3 = V1s[r * CC + c0 + 3] + acc[i][3];
        float s = v0 + v1 + v2 + v3;
        float q = v0 * v0 + v1 * v1 + v2 * v2 + v3 * v3;
#pragma unroll
        for (int off = 16; off; off >>= 1) {
            s += __shfl_xor_sync(0xffffffffu, s, off);
            q += __shfl_xor_sync(0xffffffffu, q, off);
        }
        float mean = s * (1.0f / 128.0f);
        float var = q * (1.0f / 128.0f) - mean * mean;
        float rs = rsqrtf(var + EPSLN);
        float mv = mask_V[blockIdx.x * 32 + r];
        float4 o;
        o.x = (g2[c0 + 0] * (v0 - mean) * rs + b2[c0 + 0]) * mv;
        o.y = (g2[c0 + 1] * (v1 - mean) * rs + b2[c0 + 1]) * mv;
        o.z = (g2[c0 + 2] * (v2 - mean) * rs + b2[c0 + 2]) * mv;
        o.w = (g2[c0 + 3] * (v3 - mean) * rs + b2[c0 + 3]) * mv;
        *(float4*)(out + base + (size_t)r * CC + c0) = o;
    }
}

// ---------------------------------------------------------------------------
extern "C" void kernel_launch(void* const* d_in, const int* in_sizes, int n_in,
                              void* d_out, int out_size) {
    const float* h_V = (const float*)d_in[0];
    const float* h_E = (const float*)d_in[1];
    const int* E_idx = (const int*)d_in[2];
    const float* mask_V = (const float*)d_in[3];
    const float* mask_attend = (const float*)d_in[4];
    const float* W1_w = (const float*)d_in[5];
    const float* W1_b = (const float*)d_in[6];
    const float* W2_w = (const float*)d_in[7];
    const float* W2_b = (const float*)d_in[8];
    const float* W3_w = (const float*)d_in[9];
    const float* W3_b = (const float*)d_in[10];
    const float* W11_w = (const float*)d_in[11];
    const float* W11_b = (const float*)d_in[12];
    const float* W12_w = (const float*)d_in[13];
    const float* W12_b = (const float*)d_in[14];
    const float* W13_w = (const float*)d_in[15];
    const float* W13_b = (const float*)d_in[16];
    const float* Win_w = (const float*)d_in[17];
    const float* Win_b = (const float*)d_in[18];
    const float* Wout_w = (const float*)d_in[19];
    const float* Wout_b = (const float*)d_in[20];
    const float* g1 = (const float*)d_in[21];
    const float* b1 = (const float*)d_in[22];
    const float* g2 = (const float*)d_in[23];
    const float* b2 = (const float*)d_in[24];
    const float* g3 = (const float*)d_in[25];
    const float* b3 = (const float*)d_in[26];

    float* out_hV = (float*)d_out;
    float* out_hE = out_hV + (size_t)BN * CC;

    const int SMEM_PRE = (4096 + 16384) * 4;          // 80 KB
    const int SMEM_FFN = (4096 + 16384 + 16384) * 4;  // 144 KB

    cudaFuncSetAttribute(nodepre_kernel, cudaFuncAttributeMaxDynamicSharedMemorySize, SMEM_PRE);
    cudaFuncSetAttribute(ffn_kernel, cudaFuncAttributeMaxDynamicSharedMemorySize, SMEM_FFN);
    cudaFuncSetAttribute(edge_mma_kernel<false>, cudaFuncAttributeMaxDynamicSharedMemorySize, SMEM_EDGE_DYN);
    cudaFuncSetAttribute(edge_mma_kernel<true>, cudaFuncAttributeMaxDynamicSharedMemorySize, SMEM_EDGE_DYN);

    prep_weights<<<6, 256>>>(W1_w + CC * CC, W2_w, W3_w, W11_w + CC * CC, W12_w, W13_w);
    nodepre_kernel<<<BN / 32, 512, SMEM_PRE>>>(h_V, W1_w, W1_b);
    edge_mma_kernel<false><<<148, 384, SMEM_EDGE_DYN>>>(h_E, E_idx, mask_attend, 0,
                                                        W2_b, W3_b, g3, b3, out_hE);
    ffn_kernel<<<BN / 32, 512, SMEM_FFN>>>(h_V, Win_w, Win_b, Wout_w, Wout_b,
                                           g1, b1, g2, b2, mask_V, out_hV);
    nodepre_kernel<<<BN / 32, 512, SMEM_PRE>>>(out_hV, W11_w, W11_b);
    edge_mma_kernel<true><<<148, 384, SMEM_EDGE_DYN>>>(h_E, E_idx, mask_attend, 1,
                                                       W12_b, W13_b, g3, b3, out_hE);
}

// round 11
// speedup vs baseline: 1.3863x; 1.1484x over previous
#include <cuda_runtime.h>
#include <cuda_fp16.h>
#include <math.h>
#include <stdint.h>

#define BB 2
#define NN 2048
#define KK 48
#define CC 128
#define FFD 512
#define BN (BB * NN)
#define EPSLN 1e-5f
#define INV_SCALE (1.0f / 30.0f)

// ---------------- device scratch ----------------
__device__ float g_Pa[BN * CC];   // h_V @ W1a + b1
__device__ float g_Pc[BN * CC];   // h_V @ W1c
__device__ float g_dh[BN * CC];   // masked message sum
// 6 weight images (2 sets x 3 layers), 128x128 fp16, HMMA B-fragment order
__device__ __half g_Wimg[6 * 16384];

__device__ __forceinline__ float gelu_f(float x) {
    return 0.5f * x * (1.0f + erff(x * 0.70710678118654752f));
}
__device__ __forceinline__ uint32_t pack_h2(float a, float b) {
    __half2 h; h.x = __float2half_rn(a); h.y = __float2half_rn(b);
    return *reinterpret_cast<uint32_t*>(&h);
}
__device__ __forceinline__ void mma16816(float c[4], const uint32_t a[4],
                                         uint32_t b0, uint32_t b1) {
    asm volatile(
        "mma.sync.aligned.m16n8k16.row.col.f32.f16.f16.f32 "
        "{%0,%1,%2,%3}, {%4,%5,%6,%7}, {%8,%9}, {%0,%1,%2,%3};"
        : "+f"(c[0]), "+f"(c[1]), "+f"(c[2]), "+f"(c[3])
        : "r"(a[0]), "r"(a[1]), "r"(a[2]), "r"(a[3]), "r"(b0), "r"(b1));
}

// ---------------------------------------------------------------------------
// Weight prep: 6 fp16 images in HMMA B-fragment order (proven layout).
// ---------------------------------------------------------------------------
__global__ void prep_weights(const float* __restrict__ A0, const float* __restrict__ A1,
                             const float* __restrict__ A2, const float* __restrict__ B0,
                             const float* __restrict__ B1, const float* __restrict__ B2) {
    const float* srcs[6] = {A0, A1, A2, B0, B1, B2};
    int img = blockIdx.x;                      // set*3 + layer
    const float* s = srcs[img];
    __half* dst = g_Wimg + (size_t)img * 16384;
    for (int e = threadIdx.x; e < 16384; e += blockDim.x) {
        int k = e >> 7, n = e & 127;
        int kk = k & 15;
        int t = (kk & 7) >> 1, hi8 = kk >> 3, idx = kk & 1;
        int lane = (n & 7) * 4 + t;
        int chunk = (n >> 3) * 8 + (k >> 4);
        dst[chunk * 128 + lane * 4 + hi8 * 2 + idx] = __float2half_rn(s[e]);
    }
}

// ---------------------------------------------------------------------------
// HMMA edge MLP — single fp16 MMA per k-step.
// ---------------------------------------------------------------------------
#define A_STRIDE_W 68
#define A_WORDS (KK * A_STRIDE_W)
#define SMEM_W_BYTES 98304                       // 3 images x 32 KB
#define SMEM_EDGE_DYN (SMEM_W_BYTES + A_WORDS * 4)

template <bool EDGE_OUT>
__global__ void __launch_bounds__(384, 1) edge_mma_kernel(
    const float* __restrict__ h_E, const int* __restrict__ E_idx,
    const float* __restrict__ mask_attend, int wset,
    const float* __restrict__ b2v, const float* __restrict__ b3v,
    const float* __restrict__ g3v, const float* __restrict__ b3ln,
    float* __restrict__ outp) {
    extern __shared__ uint32_t smem[];
    uint32_t* smW = smem;
    uint32_t* smA = smem + (SMEM_W_BYTES / 4);

    __shared__ int s_idx[KK];
    __shared__ float s_mask[KK];
    __shared__ float s_b2[CC], s_b3[CC], s_g3[CC], s_bl[CC];
    __shared__ float s_red[KK][4][2];
    __shared__ float s_part[3][CC];

    const int tid = threadIdx.x, lane = tid & 31, wid = tid >> 5;
    const int g = lane >> 2, t = lane & 3;
    const int mtile = wid >> 2, nchunk = wid & 3;
    const int m0 = mtile * 16, n0 = nchunk * 32;
    const int ntg0 = nchunk * 4;

    {   // 96KB weight copy once per block
        const float4* src = (const float4*)(g_Wimg + (size_t)wset * 3 * 16384);
        float4* dst = (float4*)smW;
        for (int i = tid; i < 6144; i += 384) dst[i] = src[i];
    }
    if (tid < CC) {
        s_b2[tid] = b2v[tid];
        s_b3[tid] = b3v[tid];
        if (EDGE_OUT) { s_g3[tid] = g3v[tid]; s_bl[tid] = b3ln[tid]; }
    }

    const int r_lo = m0 + g, r_hi = m0 + g + 8;

    // prefetch first node's h_E tile
    float4 r_he[4];
    int node = blockIdx.x;
    if (node < BN) {
        const float4* he4 = (const float4*)(h_E + (size_t)node * (KK * CC));
#pragma unroll
        for (int i = 0; i < 4; ++i) r_he[i] = he4[tid + 384 * i];
    }

    for (; node < BN; node += gridDim.x) {
        __syncthreads();

        if (tid < KK) {
            s_idx[tid] = E_idx[node * KK + tid];
            s_mask[tid] = mask_attend[node * KK + tid];
        }
#pragma unroll
        for (int i = 0; i < 4; ++i) {
            int idx4 = tid + 384 * i;
            float4 v = r_he[i];
            int row = idx4 >> 5, colw = (idx4 & 31) * 2;
            int w = row * A_STRIDE_W + colw;
            smA[w] = pack_h2(v.x, v.y);
            smA[w + 1] = pack_h2(v.z, v.w);
        }
        __syncthreads();

        // prefetch Pa + neighbor Pc rows for layer-0 epilogue
        float2 pfa[4], pf0[4], pf1[4];
        {
            int gb = (node >> 11) * NN;
            int nbr0 = gb + s_idx[r_lo];
            int nbr1 = gb + s_idx[r_hi];
#pragma unroll
            for (int nt = 0; nt < 4; ++nt) {
                int c = n0 + nt * 8 + t * 2;
                pfa[nt] = *(const float2*)(g_Pa + (size_t)node * CC + c);
                pf0[nt] = *(const float2*)(g_Pc + (size_t)nbr0 * CC + c);
                pf1[nt] = *(const float2*)(g_Pc + (size_t)nbr1 * CC + c);
            }
        }

        for (int layer = 0; layer < 3; ++layer) {
            if (layer == 2) {
                int nn = node + gridDim.x;
                if (nn < BN) {
                    const float4* he4 = (const float4*)(h_E + (size_t)nn * (KK * CC));
#pragma unroll
                    for (int i = 0; i < 4; ++i) r_he[i] = he4[tid + 384 * i];
                }
            }

            float acc[4][4];
#pragma unroll
            for (int nt = 0; nt < 4; ++nt)
#pragma unroll
                for (int j = 0; j < 4; ++j) acc[nt][j] = 0.0f;

            const uint2* WH = (const uint2*)smW + layer * 4096;
#pragma unroll
            for (int ks = 0; ks < 8; ++ks) {
                uint32_t a[4];
                int aw = r_lo * A_STRIDE_W + ks * 8 + t;
                int aw2 = r_hi * A_STRIDE_W + ks * 8 + t;
                a[0] = smA[aw];     a[1] = smA[aw2];
                a[2] = smA[aw + 4]; a[3] = smA[aw2 + 4];
#pragma unroll
                for (int nt = 0; nt < 4; ++nt) {
                    int chunk = (ntg0 + nt) * 8 + ks;
                    uint2 bh = WH[chunk * 32 + lane];
                    mma16816(acc[nt], a, bh.x, bh.y);
                }
            }
            __syncthreads();   // all A reads done before rewrite

            if (layer < 2) {
#pragma unroll
                for (int nt = 0; nt < 4; ++nt) {
                    int c = n0 + nt * 8 + t * 2;
                    float a0, a1, b0, b1;
                    if (layer == 0) {
                        a0 = pfa[nt].x + pf0[nt].x; a1 = pfa[nt].y + pf0[nt].y;
                        b0 = pfa[nt].x + pf1[nt].x; b1 = pfa[nt].y + pf1[nt].y;
                    } else {
                        a0 = s_b2[c]; a1 = s_b2[c + 1];
                        b0 = a0; b1 = a1;
                    }
                    int w0 = r_lo * A_STRIDE_W + c / 2;
                    int w1 = r_hi * A_STRIDE_W + c / 2;
                    smA[w0] = pack_h2(gelu_f(acc[nt][0] + a0), gelu_f(acc[nt][1] + a1));
                    smA[w1] = pack_h2(gelu_f(acc[nt][2] + b0), gelu_f(acc[nt][3] + b1));
                }
                __syncthreads();
            } else if (!EDGE_OUT) {
                // masked K-sum via g-axis shuffles (lanes t, t+4, ..., t+28)
                float mlo = s_mask[r_lo], mhi = s_mask[r_hi];
                float cs[8];
#pragma unroll
                for (int nt = 0; nt < 4; ++nt) {
                    int c = n0 + nt * 8 + t * 2;
                    cs[nt * 2 + 0] = mlo * (acc[nt][0] + s_b3[c]) +
                                     mhi * (acc[nt][2] + s_b3[c]);
                    cs[nt * 2 + 1] = mlo * (acc[nt][1] + s_b3[c + 1]) +
                                     mhi * (acc[nt][3] + s_b3[c + 1]);
                }
#pragma unroll
                for (int off = 4; off <= 16; off <<= 1)
#pragma unroll
                    for (int j = 0; j < 8; ++j)
                        cs[j] += __shfl_xor_sync(0xffffffffu, cs[j], off);
                if (g == 0) {
#pragma unroll
                    for (int nt = 0; nt < 4; ++nt) {
                        int c = n0 + nt * 8 + t * 2;
                        s_part[mtile][c] = cs[nt * 2];
                        s_part[mtile][c + 1] = cs[nt * 2 + 1];
                    }
                }
                __syncthreads();
                if (tid < CC)
                    g_dh[(size_t)node * CC + tid] =
                        s_part[0][tid] + s_part[1][tid] + s_part[2][tid];
            } else {
                const float* he = h_E + (size_t)node * (KK * CC);
                float v[4][4];
                float sl = 0.0f, ql = 0.0f, sh = 0.0f, qh = 0.0f;
#pragma unroll
                for (int nt = 0; nt < 4; ++nt) {
                    int c = n0 + nt * 8 + t * 2;
                    float2 e0 = *(const float2*)(he + r_lo * CC + c);
                    float2 e1 = *(const float2*)(he + r_hi * CC + c);
                    v[nt][0] = acc[nt][0] + s_b3[c] + e0.x;
                    v[nt][1] = acc[nt][1] + s_b3[c + 1] + e0.y;
                    v[nt][2] = acc[nt][2] + s_b3[c] + e1.x;
                    v[nt][3] = acc[nt][3] + s_b3[c + 1] + e1.y;
                    sl += v[nt][0] + v[nt][1]; ql += v[nt][0] * v[nt][0] + v[nt][1] * v[nt][1];
                    sh += v[nt][2] + v[nt][3]; qh += v[nt][2] * v[nt][2] + v[nt][3] * v[nt][3];
                }
#pragma unroll
                for (int off = 1; off <= 2; off <<= 1) {
                    sl += __shfl_xor_sync(0xffffffffu, sl, off);
                    ql += __shfl_xor_sync(0xffffffffu, ql, off);
                    sh += __shfl_xor_sync(0xffffffffu, sh, off);
                    qh += __shfl_xor_sync(0xffffffffu, qh, off);
                }
                if (t == 0) {
                    s_red[r_lo][nchunk][0] = sl; s_red[r_lo][nchunk][1] = ql;
                    s_red[r_hi][nchunk][0] = sh; s_red[r_hi][nchunk][1] = qh;
                }
                __syncthreads();
                float S0 = 0, Q0 = 0, S1 = 0, Q1 = 0;
#pragma unroll
                for (int w = 0; w < 4; ++w) {
                    S0 += s_red[r_lo][w][0]; Q0 += s_red[r_lo][w][1];
                    S1 += s_red[r_hi][w][0]; Q1 += s_red[r_hi][w][1];
                }
                float m0f = S0 * (1.0f / 128.0f);
                float rs0 = rsqrtf(Q0 * (1.0f / 128.0f) - m0f * m0f + EPSLN);
                float m1f = S1 * (1.0f / 128.0f);
                float rs1 = rsqrtf(Q1 * (1.0f / 128.0f) - m1f * m1f + EPSLN);
                float* op = outp + (size_t)node * (KK * CC);
#pragma unroll
                for (int nt = 0; nt < 4; ++nt) {
                    int c = n0 + nt * 8 + t * 2;
                    float2 o0, o1;
                    o0.x = s_g3[c] * (v[nt][0] - m0f) * rs0 + s_bl[c];
                    o0.y = s_g3[c + 1] * (v[nt][1] - m0f) * rs0 + s_bl[c + 1];
                    o1.x = s_g3[c] * (v[nt][2] - m1f) * rs1 + s_bl[c];
                    o1.y = s_g3[c + 1] * (v[nt][3] - m1f) * rs1 + s_bl[c + 1];
                    *(float2*)(op + r_lo * CC + c) = o0;
                    *(float2*)(op + r_hi * CC + c) = o1;
                }
            }
        }
    }
}

// ---------------------------------------------------------------------------
// Scalar node kernels — proven Round-6 versions (32 nodes/block).
// ---------------------------------------------------------------------------
template <int R>
__device__ __forceinline__ void mm_tile(float acc[R][4], const float* Xs, int xstride4,
                                        const float* Ws, int r0, int lane) {
    const float4* X4 = (const float4*)Xs;
    const float4* W4 = (const float4*)Ws;
#pragma unroll 4
    for (int kq = 0; kq < 32; ++kq) {
        float4 w0 = W4[(4 * kq + 0) * 32 + lane];
        float4 w1 = W4[(4 * kq + 1) * 32 + lane];
        float4 w2 = W4[(4 * kq + 2) * 32 + lane];
        float4 w3 = W4[(4 * kq + 3) * 32 + lane];
#pragma unroll
        for (int i = 0; i < R; ++i) {
            float4 x = X4[(r0 + i) * xstride4 + kq];
            acc[i][0] = fmaf(x.x, w0.x, acc[i][0]); acc[i][1] = fmaf(x.x, w0.y, acc[i][1]);
            acc[i][2] = fmaf(x.x, w0.z, acc[i][2]); acc[i][3] = fmaf(x.x, w0.w, acc[i][3]);
            acc[i][0] = fmaf(x.y, w1.x, acc[i][0]); acc[i][1] = fmaf(x.y, w1.y, acc[i][1]);
            acc[i][2] = fmaf(x.y, w1.z, acc[i][2]); acc[i][3] = fmaf(x.y, w1.w, acc[i][3]);
            acc[i][0] = fmaf(x.z, w2.x, acc[i][0]); acc[i][1] = fmaf(x.z, w2.y, acc[i][1]);
            acc[i][2] = fmaf(x.z, w2.z, acc[i][2]); acc[i][3] = fmaf(x.z, w2.w, acc[i][3]);
            acc[i][0] = fmaf(x.w, w3.x, acc[i][0]); acc[i][1] = fmaf(x.w, w3.y, acc[i][1]);
            acc[i][2] = fmaf(x.w, w3.z, acc[i][2]); acc[i][3] = fmaf(x.w, w3.w, acc[i][3]);
        }
    }
}

__global__ void __launch_bounds__(512) nodepre_kernel(
    const float* __restrict__ hV, const float* __restrict__ W1,
    const float* __restrict__ b1) {
    extern __shared__ float sm[];
    float* Vs = sm;
    float* Ws = sm + 4096;
    int tid = threadIdx.x, lane = tid & 31, warp = tid >> 5;
    size_t base = (size_t)blockIdx.x * 32 * CC;
    {
        const float4* src = (const float4*)(hV + base);
        float4* dst = (float4*)Vs;
#pragma unroll
        for (int e = 0; e < 2; ++e) dst[tid + 512 * e] = src[tid + 512 * e];
    }
    {
        const float4* src = (const float4*)W1;
        float4* dst = (float4*)Ws;
#pragma unroll
        for (int e = 0; e < 8; ++e) dst[tid + 512 * e] = src[tid + 512 * e];
    }
    __syncthreads();
    int r0 = warp * 2, c0 = lane * 4;
    float acc[2][4];
#pragma unroll
    for (int j = 0; j < 4; ++j) { float b = b1[c0 + j]; acc[0][j] = b; acc[1][j] = b; }
    mm_tile<2>(acc, Vs, 32, Ws, r0, lane);
#pragma unroll
    for (int i = 0; i < 2; ++i)
#pragma unroll
        for (int j = 0; j < 4; ++j)
            g_Pa[base + (size_t)(r0 + i) * CC + c0 + j] = acc[i][j];
    __syncthreads();
    {
        const float4* src = (const float4*)(W1 + 2 * CC * CC);
        float4* dst = (float4*)Ws;
#pragma unroll
        for (int e = 0; e < 8; ++e) dst[tid + 512 * e] = src[tid + 512 * e];
    }
    __syncthreads();
#pragma unroll
    for (int i = 0; i < 2; ++i)
#pragma unroll
        for (int j = 0; j < 4; ++j) acc[i][j] = 0.0f;
    mm_tile<2>(acc, Vs, 32, Ws, r0, lane);
#pragma unroll
    for (int i = 0; i < 2; ++i)
#pragma unroll
        for (int j = 0; j < 4; ++j)
            g_Pc[base + (size_t)(r0 + i) * CC + c0 + j] = acc[i][j];
}

__global__ void __launch_bounds__(512) ffn_kernel(
    const float* __restrict__ hV,
    const float* __restrict__ Win_w, const float* __restrict__ Win_b,
    const float* __restrict__ Wout_w, const float* __restrict__ Wout_b,
    const float* __restrict__ g1, const float* __restrict__ b1,
    const float* __restrict__ g2, const float* __restrict__ b2,
    const float* __restrict__ mask_V, float* __restrict__ out) {
    extern __shared__ float sm[];
    float* V1s = sm;
    float* Ts = sm + 4096;
    float* Ws = sm + 4096 + 16384;
    int tid = threadIdx.x, lane = tid & 31, warp = tid >> 5;
    size_t base = (size_t)blockIdx.x * 32 * CC;
    int c0 = lane * 4, r0 = warp * 2;
#pragma unroll
    for (int i = 0; i < 2; ++i) {
        int r = r0 + i;
        float4 xv = *(const float4*)(hV + base + (size_t)r * CC + c0);
        float4 dv = *(const float4*)(&g_dh[base + (size_t)r * CC + c0]);
        float x0 = xv.x + dv.x * INV_SCALE, x1 = xv.y + dv.y * INV_SCALE;
        float x2 = xv.z + dv.z * INV_SCALE, x3 = xv.w + dv.w * INV_SCALE;
        float s = x0 + x1 + x2 + x3;
        float q = x0 * x0 + x1 * x1 + x2 * x2 + x3 * x3;
#pragma unroll
        for (int off = 16; off; off >>= 1) {
            s += __shfl_xor_sync(0xffffffffu, s, off);
            q += __shfl_xor_sync(0xffffffffu, q, off);
        }
        float mean = s * (1.0f / 128.0f);
        float var = q * (1.0f / 128.0f) - mean * mean;
        float rs = rsqrtf(var + EPSLN);
        float4 o;
        o.x = g1[c0 + 0] * (x0 - mean) * rs + b1[c0 + 0];
        o.y = g1[c0 + 1] * (x1 - mean) * rs + b1[c0 + 1];
        o.z = g1[c0 + 2] * (x2 - mean) * rs + b1[c0 + 2];
        o.w = g1[c0 + 3] * (x3 - mean) * rs + b1[c0 + 3];
        *(float4*)(V1s + r * CC + c0) = o;
    }
    __syncthreads();
    for (int ct = 0; ct < 4; ++ct) {
        if (ct) __syncthreads();
        for (int e = tid; e < 4096; e += 512) {
            int k = e >> 5, cq = e & 31;
            ((float4*)Ws)[e] = ((const float4*)Win_w)[k * 128 + ct * 32 + cq];
        }
        __syncthreads();
        float acc[2][4];
#pragma unroll
        for (int j = 0; j < 4; ++j) {
            float b = Win_b[ct * 128 + c0 + j];
            acc[0][j] = b; acc[1][j] = b;
        }
        mm_tile<2>(acc, V1s, 32, Ws, r0, lane);
#pragma unroll
        for (int i = 0; i < 2; ++i)
#pragma unroll
            for (int j = 0; j < 4; ++j)
                Ts[(r0 + i) * FFD + ct * 128 + c0 + j] = gelu_f(acc[i][j]);
    }
    __syncthreads();
    float acc[2][4];
#pragma unroll
    for (int j = 0; j < 4; ++j) {
        float b = Wout_b[c0 + j];
        acc[0][j] = b; acc[1][j] = b;
    }
    for (int kt = 0; kt < 4; ++kt) {
        if (kt) __syncthreads();
        for (int e = tid; e < 4096; e += 512)
            ((float4*)Ws)[e] = ((const float4*)Wout_w)[kt * 4096 + e];
        __syncthreads();
        mm_tile<2>(acc, Ts + kt * 128, 128, Ws, r0, lane);
    }
#pragma unroll
    for (int i = 0; i < 2; ++i) {
        int r = r0 + i;
        float v0 = V1s[r * CC + c0 + 0] + acc[i][0];
        float v1 = V1s[r * CC + c0 + 1] + acc[i][1];
        float v2 = V1s[r * CC + c0 + 2] + acc[i][2];
        float v3 = V1s[r * CC + c0 + 3] + acc[i][3];
        float s = v0 + v1 + v2 + v3;
        float q = v0 * v0 + v1 * v1 + v2 * v2 + v3 * v3;
#pragma unroll
        for (int off = 16; off; off >>= 1) {
            s += __shfl_xor_sync(0xffffffffu, s, off);
            q += __shfl_xor_sync(0xffffffffu, q, off);
        }
        float mean = s * (1.0f / 128.0f);
        float var = q * (1.0f / 128.0f) - mean * mean;
        float rs = rsqrtf(var + EPSLN);
        float mv = mask_V[blockIdx.x * 32 + r];
        float4 o;
        o.x = (g2[c0 + 0] * (v0 - mean) * rs + b2[c0 + 0]) * mv;
        o.y = (g2[c0 + 1] * (v1 - mean) * rs + b2[c0 + 1]) * mv;
        o.z = (g2[c0 + 2] * (v2 - mean) * rs + b2[c0 + 2]) * mv;
        o.w = (g2[c0 + 3] * (v3 - mean) * rs + b2[c0 + 3]) * mv;
        *(float4*)(out + base + (size_t)r * CC + c0) = o;
    }
}

// ---------------------------------------------------------------------------
extern "C" void kernel_launch(void* const* d_in, const int* in_sizes, int n_in,
                              void* d_out, int out_size) {
    const float* h_V = (const float*)d_in[0];
    const float* h_E = (const float*)d_in[1];
    const int* E_idx = (const int*)d_in[2];
    const float* mask_V = (const float*)d_in[3];
    const float* mask_attend = (const float*)d_in[4];
    const float* W1_w = (const float*)d_in[5];
    const float* W1_b = (const float*)d_in[6];
    const float* W2_w = (const float*)d_in[7];
    const float* W2_b = (const float*)d_in[8];
    const float* W3_w = (const float*)d_in[9];
    const float* W3_b = (const float*)d_in[10];
    const float* W11_w = (const float*)d_in[11];
    const float* W11_b = (const float*)d_in[12];
    const float* W12_w = (const float*)d_in[13];
    const float* W12_b = (const float*)d_in[14];
    const float* W13_w = (const float*)d_in[15];
    const float* W13_b = (const float*)d_in[16];
    const float* Win_w = (const float*)d_in[17];
    const float* Win_b = (const float*)d_in[18];
    const float* Wout_w = (const float*)d_in[19];
    const float* Wout_b = (const float*)d_in[20];
    const float* g1 = (const float*)d_in[21];
    const float* b1 = (const float*)d_in[22];
    const float* g2 = (const float*)d_in[23];
    const float* b2 = (const float*)d_in[24];
    const float* g3 = (const float*)d_in[25];
    const float* b3 = (const float*)d_in[26];

    float* out_hV = (float*)d_out;
    float* out_hE = out_hV + (size_t)BN * CC;

    const int SMEM_PRE = (4096 + 16384) * 4;          // 80 KB
    const int SMEM_FFN = (4096 + 16384 + 16384) * 4;  // 144 KB

    cudaFuncSetAttribute(nodepre_kernel, cudaFuncAttributeMaxDynamicSharedMemorySize, SMEM_PRE);
    cudaFuncSetAttribute(ffn_kernel, cudaFuncAttributeMaxDynamicSharedMemorySize, SMEM_FFN);
    cudaFuncSetAttribute(edge_mma_kernel<false>, cudaFuncAttributeMaxDynamicSharedMemorySize, SMEM_EDGE_DYN);
    cudaFuncSetAttribute(edge_mma_kernel<true>, cudaFuncAttributeMaxDynamicSharedMemorySize, SMEM_EDGE_DYN);

    prep_weights<<<6, 256>>>(W1_w + CC * CC, W2_w, W3_w, W11_w + CC * CC, W12_w, W13_w);
    nodepre_kernel<<<BN / 32, 512, SMEM_PRE>>>(h_V, W1_w, W1_b);
    edge_mma_kernel<false><<<148, 384, SMEM_EDGE_DYN>>>(h_E, E_idx, mask_attend, 0,
                                                        W2_b, W3_b, g3, b3, out_hE);
    ffn_kernel<<<BN / 32, 512, SMEM_FFN>>>(h_V, Win_w, Win_b, Wout_w, Wout_b,
                                           g1, b1, g2, b2, mask_V, out_hV);
    nodepre_kernel<<<BN / 32, 512, SMEM_PRE>>>(out_hV, W11_w, W11_b);
    edge_mma_kernel<true><<<148, 384, SMEM_EDGE_DYN>>>(h_E, E_idx, mask_attend, 1,
                                                       W12_b, W13_b, g3, b3, out_hE);
}

// round 12
// speedup vs baseline: 1.5651x; 1.1289x over previous
#include <cuda_runtime.h>
#include <cuda_fp16.h>
#include <math.h>
#include <stdint.h>

#define BB 2
#define NN 2048
#define KK 48
#define CC 128
#define FFD 512
#define BN (BB * NN)
#define EPSLN 1e-5f
#define INV_SCALE (1.0f / 30.0f)

// ---------------- device scratch ----------------
__device__ float g_Pa[BN * CC];   // h_V @ W1a + b1
__device__ float g_Pc[BN * CC];   // h_V @ W1c
__device__ float g_dh[BN * CC];   // masked message sum
// 6 weight images (2 sets x 3 layers), 128x128 fp16, HMMA B-fragment order
__device__ __half g_Wimg[6 * 16384];

__device__ __forceinline__ float gelu_f(float x) {
    return 0.5f * x * (1.0f + erff(x * 0.70710678118654752f));
}
__device__ __forceinline__ uint32_t pack_h2(float a, float b) {
    __half2 h; h.x = __float2half_rn(a); h.y = __float2half_rn(b);
    return *reinterpret_cast<uint32_t*>(&h);
}
__device__ __forceinline__ void mma16816(float c[4], const uint32_t a[4],
                                         uint32_t b0, uint32_t b1) {
    asm volatile(
        "mma.sync.aligned.m16n8k16.row.col.f32.f16.f16.f32 "
        "{%0,%1,%2,%3}, {%4,%5,%6,%7}, {%8,%9}, {%0,%1,%2,%3};"
        : "+f"(c[0]), "+f"(c[1]), "+f"(c[2]), "+f"(c[3])
        : "r"(a[0]), "r"(a[1]), "r"(a[2]), "r"(a[3]), "r"(b0), "r"(b1));
}

// ---------------------------------------------------------------------------
// Weight prep: 6 fp16 images in HMMA B-fragment order (proven layout).
// ---------------------------------------------------------------------------
__global__ void prep_weights(const float* __restrict__ A0, const float* __restrict__ A1,
                             const float* __restrict__ A2, const float* __restrict__ B0,
                             const float* __restrict__ B1, const float* __restrict__ B2) {
    const float* srcs[6] = {A0, A1, A2, B0, B1, B2};
    int img = blockIdx.x;                      // set*3 + layer
    const float* s = srcs[img];
    __half* dst = g_Wimg + (size_t)img * 16384;
    for (int e = threadIdx.x; e < 16384; e += blockDim.x) {
        int k = e >> 7, n = e & 127;
        int kk = k & 15;
        int t = (kk & 7) >> 1, hi8 = kk >> 3, idx = kk & 1;
        int lane = (n & 7) * 4 + t;
        int chunk = (n >> 3) * 8 + (k >> 4);
        dst[chunk * 128 + lane * 4 + hi8 * 2 + idx] = __float2half_rn(s[e]);
    }
}

// ---------------------------------------------------------------------------
// HMMA edge MLP — single fp16 MMA per k-step; 2 CTAs/SM for MMA/epilogue overlap.
// ---------------------------------------------------------------------------
#define A_STRIDE_W 68
#define A_WORDS (KK * A_STRIDE_W)
#define SMEM_W_BYTES 98304                       // 3 images x 32 KB
#define SMEM_EDGE_DYN (SMEM_W_BYTES + A_WORDS * 4)   // 111360 B

template <bool EDGE_OUT>
__global__ void __launch_bounds__(384, 2) edge_mma_kernel(
    const float* __restrict__ h_E, const int* __restrict__ E_idx,
    const float* __restrict__ mask_attend, int wset,
    const float* __restrict__ b2v, const float* __restrict__ b3v,
    const float* __restrict__ g3v, const float* __restrict__ b3ln,
    float* __restrict__ outp) {
    extern __shared__ uint32_t smem[];
    uint32_t* smW = smem;
    uint32_t* smA = smem + (SMEM_W_BYTES / 4);

    __shared__ float s_b2[CC], s_b3[CC], s_g3[CC], s_bl[CC];
    __shared__ float s_red[KK * 4 * 2];          // 384 floats; aliased as s_part[3][CC]
    float* s_part = s_red;

    const int tid = threadIdx.x, lane = tid & 31, wid = tid >> 5;
    const int g = lane >> 2, t = lane & 3;
    const int mtile = wid >> 2, nchunk = wid & 3;
    const int m0 = mtile * 16, n0 = nchunk * 32;
    const int ntg0 = nchunk * 4;

    {   // 96KB weight copy once per block
        const float4* src = (const float4*)(g_Wimg + (size_t)wset * 3 * 16384);
        float4* dst = (float4*)smW;
        for (int i = tid; i < 6144; i += 384) dst[i] = src[i];
    }
    if (tid < CC) {
        s_b2[tid] = b2v[tid];
        s_b3[tid] = b3v[tid];
        if (EDGE_OUT) { s_g3[tid] = g3v[tid]; s_bl[tid] = b3ln[tid]; }
    }

    const int r_lo = m0 + g, r_hi = m0 + g + 8;

    for (int node = blockIdx.x; node < BN; node += gridDim.x) {
        __syncthreads();   // previous iteration's smA reads complete

        // prologue: pack h_E tile to fp16 in SMEM A
#pragma unroll
        for (int i = 0; i < 4; ++i) {
            int idx4 = tid + 384 * i;
            float4 v = ((const float4*)(h_E + (size_t)node * (KK * CC)))[idx4];
            int row = idx4 >> 5, colw = (idx4 & 31) * 2;
            int w = row * A_STRIDE_W + colw;
            smA[w] = pack_h2(v.x, v.y);
            smA[w + 1] = pack_h2(v.z, v.w);
        }
        __syncthreads();

        for (int layer = 0; layer < 3; ++layer) {
            float acc[4][4];
#pragma unroll
            for (int nt = 0; nt < 4; ++nt)
#pragma unroll
                for (int j = 0; j < 4; ++j) acc[nt][j] = 0.0f;

            const uint2* WH = (const uint2*)smW + layer * 4096;
#pragma unroll
            for (int ks = 0; ks < 8; ++ks) {
                uint32_t a[4];
                int aw = r_lo * A_STRIDE_W + ks * 8 + t;
                int aw2 = r_hi * A_STRIDE_W + ks * 8 + t;
                a[0] = smA[aw];     a[1] = smA[aw2];
                a[2] = smA[aw + 4]; a[3] = smA[aw2 + 4];
#pragma unroll
                for (int nt = 0; nt < 4; ++nt) {
                    int chunk = (ntg0 + nt) * 8 + ks;
                    uint2 bh = WH[chunk * 32 + lane];
                    mma16816(acc[nt], a, bh.x, bh.y);
                }
            }
            __syncthreads();   // all A reads done before rewrite

            if (layer < 2) {
                float a0v[4][2], b0v[4][2];
                if (layer == 0) {
                    int gb = (node >> 11) * NN;
                    int nbr0 = gb + E_idx[node * KK + r_lo];
                    int nbr1 = gb + E_idx[node * KK + r_hi];
#pragma unroll
                    for (int nt = 0; nt < 4; ++nt) {
                        int c = n0 + nt * 8 + t * 2;
                        float2 pa = *(const float2*)(g_Pa + (size_t)node * CC + c);
                        float2 p0 = *(const float2*)(g_Pc + (size_t)nbr0 * CC + c);
                        float2 p1 = *(const float2*)(g_Pc + (size_t)nbr1 * CC + c);
                        a0v[nt][0] = pa.x + p0.x; a0v[nt][1] = pa.y + p0.y;
                        b0v[nt][0] = pa.x + p1.x; b0v[nt][1] = pa.y + p1.y;
                    }
                } else {
#pragma unroll
                    for (int nt = 0; nt < 4; ++nt) {
                        int c = n0 + nt * 8 + t * 2;
                        a0v[nt][0] = s_b2[c]; a0v[nt][1] = s_b2[c + 1];
                        b0v[nt][0] = a0v[nt][0]; b0v[nt][1] = a0v[nt][1];
                    }
                }
#pragma unroll
                for (int nt = 0; nt < 4; ++nt) {
                    int c = n0 + nt * 8 + t * 2;
                    int w0 = r_lo * A_STRIDE_W + c / 2;
                    int w1 = r_hi * A_STRIDE_W + c / 2;
                    smA[w0] = pack_h2(gelu_f(acc[nt][0] + a0v[nt][0]),
                                      gelu_f(acc[nt][1] + a0v[nt][1]));
                    smA[w1] = pack_h2(gelu_f(acc[nt][2] + b0v[nt][0]),
                                      gelu_f(acc[nt][3] + b0v[nt][1]));
                }
                __syncthreads();
            } else if (!EDGE_OUT) {
                // masked K-sum via g-axis shuffles
                float mlo = mask_attend[node * KK + r_lo];
                float mhi = mask_attend[node * KK + r_hi];
                float cs[8];
#pragma unroll
                for (int nt = 0; nt < 4; ++nt) {
                    int c = n0 + nt * 8 + t * 2;
                    cs[nt * 2 + 0] = mlo * (acc[nt][0] + s_b3[c]) +
                                     mhi * (acc[nt][2] + s_b3[c]);
                    cs[nt * 2 + 1] = mlo * (acc[nt][1] + s_b3[c + 1]) +
                                     mhi * (acc[nt][3] + s_b3[c + 1]);
                }
#pragma unroll
                for (int off = 4; off <= 16; off <<= 1)
#pragma unroll
                    for (int j = 0; j < 8; ++j)
                        cs[j] += __shfl_xor_sync(0xffffffffu, cs[j], off);
                if (g == 0) {
#pragma unroll
                    for (int nt = 0; nt < 4; ++nt) {
                        int c = n0 + nt * 8 + t * 2;
                        s_part[mtile * CC + c] = cs[nt * 2];
                        s_part[mtile * CC + c + 1] = cs[nt * 2 + 1];
                    }
                }
                __syncthreads();
                if (tid < CC)
                    g_dh[(size_t)node * CC + tid] =
                        s_part[tid] + s_part[CC + tid] + s_part[2 * CC + tid];
            } else {
                const float* he = h_E + (size_t)node * (KK * CC);
                float v[4][4];
                float sl = 0.0f, ql = 0.0f, sh = 0.0f, qh = 0.0f;
#pragma unroll
                for (int nt = 0; nt < 4; ++nt) {
                    int c = n0 + nt * 8 + t * 2;
                    float2 e0 = *(const float2*)(he + r_lo * CC + c);
                    float2 e1 = *(const float2*)(he + r_hi * CC + c);
                    v[nt][0] = acc[nt][0] + s_b3[c] + e0.x;
                    v[nt][1] = acc[nt][1] + s_b3[c + 1] + e0.y;
                    v[nt][2] = acc[nt][2] + s_b3[c] + e1.x;
                    v[nt][3] = acc[nt][3] + s_b3[c + 1] + e1.y;
                    sl += v[nt][0] + v[nt][1]; ql += v[nt][0] * v[nt][0] + v[nt][1] * v[nt][1];
                    sh += v[nt][2] + v[nt][3]; qh += v[nt][2] * v[nt][2] + v[nt][3] * v[nt][3];
                }
#pragma unroll
                for (int off = 1; off <= 2; off <<= 1) {
                    sl += __shfl_xor_sync(0xffffffffu, sl, off);
                    ql += __shfl_xor_sync(0xffffffffu, ql, off);
                    sh += __shfl_xor_sync(0xffffffffu, sh, off);
                    qh += __shfl_xor_sync(0xffffffffu, qh, off);
                }
                if (t == 0) {
                    s_red[(r_lo * 4 + nchunk) * 2 + 0] = sl;
                    s_red[(r_lo * 4 + nchunk) * 2 + 1] = ql;
                    s_red[(r_hi * 4 + nchunk) * 2 + 0] = sh;
                    s_red[(r_hi * 4 + nchunk) * 2 + 1] = qh;
                }
                __syncthreads();
                float S0 = 0, Q0 = 0, S1 = 0, Q1 = 0;
#pragma unroll
                for (int w = 0; w < 4; ++w) {
                    S0 += s_red[(r_lo * 4 + w) * 2 + 0]; Q0 += s_red[(r_lo * 4 + w) * 2 + 1];
                    S1 += s_red[(r_hi * 4 + w) * 2 + 0]; Q1 += s_red[(r_hi * 4 + w) * 2 + 1];
                }
                float m0f = S0 * (1.0f / 128.0f);
                float rs0 = rsqrtf(Q0 * (1.0f / 128.0f) - m0f * m0f + EPSLN);
                float m1f = S1 * (1.0f / 128.0f);
                float rs1 = rsqrtf(Q1 * (1.0f / 128.0f) - m1f * m1f + EPSLN);
                float* op = outp + (size_t)node * (KK * CC);
#pragma unroll
                for (int nt = 0; nt < 4; ++nt) {
                    int c = n0 + nt * 8 + t * 2;
                    float2 o0, o1;
                    o0.x = s_g3[c] * (v[nt][0] - m0f) * rs0 + s_bl[c];
                    o0.y = s_g3[c + 1] * (v[nt][1] - m0f) * rs0 + s_bl[c + 1];
                    o1.x = s_g3[c] * (v[nt][2] - m1f) * rs1 + s_bl[c];
                    o1.y = s_g3[c + 1] * (v[nt][3] - m1f) * rs1 + s_bl[c + 1];
                    *(float2*)(op + r_lo * CC + c) = o0;
                    *(float2*)(op + r_hi * CC + c) = o1;
                }
            }
        }
    }
}

// ---------------------------------------------------------------------------
// Scalar node kernels — proven Round-6 versions (32 nodes/block).
// ---------------------------------------------------------------------------
template <int R>
__device__ __forceinline__ void mm_tile(float acc[R][4], const float* Xs, int xstride4,
                                        const float* Ws, int r0, int lane) {
    const float4* X4 = (const float4*)Xs;
    const float4* W4 = (const float4*)Ws;
#pragma unroll 4
    for (int kq = 0; kq < 32; ++kq) {
        float4 w0 = W4[(4 * kq + 0) * 32 + lane];
        float4 w1 = W4[(4 * kq + 1) * 32 + lane];
        float4 w2 = W4[(4 * kq + 2) * 32 + lane];
        float4 w3 = W4[(4 * kq + 3) * 32 + lane];
#pragma unroll
        for (int i = 0; i < R; ++i) {
            float4 x = X4[(r0 + i) * xstride4 + kq];
            acc[i][0] = fmaf(x.x, w0.x, acc[i][0]); acc[i][1] = fmaf(x.x, w0.y, acc[i][1]);
            acc[i][2] = fmaf(x.x, w0.z, acc[i][2]); acc[i][3] = fmaf(x.x, w0.w, acc[i][3]);
            acc[i][0] = fmaf(x.y, w1.x, acc[i][0]); acc[i][1] = fmaf(x.y, w1.y, acc[i][1]);
            acc[i][2] = fmaf(x.y, w1.z, acc[i][2]); acc[i][3] = fmaf(x.y, w1.w, acc[i][3]);
            acc[i][0] = fmaf(x.z, w2.x, acc[i][0]); acc[i][1] = fmaf(x.z, w2.y, acc[i][1]);
            acc[i][2] = fmaf(x.z, w2.z, acc[i][2]); acc[i][3] = fmaf(x.z, w2.w, acc[i][3]);
            acc[i][0] = fmaf(x.w, w3.x, acc[i][0]); acc[i][1] = fmaf(x.w, w3.y, acc[i][1]);
            acc[i][2] = fmaf(x.w, w3.z, acc[i][2]); acc[i][3] = fmaf(x.w, w3.w, acc[i][3]);
        }
    }
}

__global__ void __launch_bounds__(512) nodepre_kernel(
    const float* __restrict__ hV, const float* __restrict__ W1,
    const float* __restrict__ b1) {
    extern __shared__ float sm[];
    float* Vs = sm;
    float* Ws = sm + 4096;
    int tid = threadIdx.x, lane = tid & 31, warp = tid >> 5;
    size_t base = (size_t)blockIdx.x * 32 * CC;
    {
        const float4* src = (const float4*)(hV + base);
        float4* dst = (float4*)Vs;
#pragma unroll
        for (int e = 0; e < 2; ++e) dst[tid + 512 * e] = src[tid + 512 * e];
    }
    {
        const float4* src = (const float4*)W1;
        float4* dst = (float4*)Ws;
#pragma unroll
        for (int e = 0; e < 8; ++e) dst[tid + 512 * e] = src[tid + 512 * e];
    }
    __syncthreads();
    int r0 = warp * 2, c0 = lane * 4;
    float acc[2][4];
#pragma unroll
    for (int j = 0; j < 4; ++j) { float b = b1[c0 + j]; acc[0][j] = b; acc[1][j] = b; }
    mm_tile<2>(acc, Vs, 32, Ws, r0, lane);
#pragma unroll
    for (int i = 0; i < 2; ++i)
#pragma unroll
        for (int j = 0; j < 4; ++j)
            g_Pa[base + (size_t)(r0 + i) * CC + c0 + j] = acc[i][j];
    __syncthreads();
    {
        const float4* src = (const float4*)(W1 + 2 * CC * CC);
        float4* dst = (float4*)Ws;
#pragma unroll
        for (int e = 0; e < 8; ++e) dst[tid + 512 * e] = src[tid + 512 * e];
    }
    __syncthreads();
#pragma unroll
    for (int i = 0; i < 2; ++i)
#pragma unroll
        for (int j = 0; j < 4; ++j) acc[i][j] = 0.0f;
    mm_tile<2>(acc, Vs, 32, Ws, r0, lane);
#pragma unroll
    for (int i = 0; i < 2; ++i)
#pragma unroll
        for (int j = 0; j < 4; ++j)
            g_Pc[base + (size_t)(r0 + i) * CC + c0 + j] = acc[i][j];
}

__global__ void __launch_bounds__(512) ffn_kernel(
    const float* __restrict__ hV,
    const float* __restrict__ Win_w, const float* __restrict__ Win_b,
    const float* __restrict__ Wout_w, const float* __restrict__ Wout_b,
    const float* __restrict__ g1, const float* __restrict__ b1,
    const float* __restrict__ g2, const float* __restrict__ b2,
    const float* __restrict__ mask_V, float* __restrict__ out) {
    extern __shared__ float sm[];
    float* V1s = sm;
    float* Ts = sm + 4096;
    float* Ws = sm + 4096 + 16384;
    int tid = threadIdx.x, lane = tid & 31, warp = tid >> 5;
    size_t base = (size_t)blockIdx.x * 32 * CC;
    int c0 = lane * 4, r0 = warp * 2;
#pragma unroll
    for (int i = 0; i < 2; ++i) {
        int r = r0 + i;
        float4 xv = *(const float4*)(hV + base + (size_t)r * CC + c0);
        float4 dv = *(const float4*)(&g_dh[base + (size_t)r * CC + c0]);
        float x0 = xv.x + dv.x * INV_SCALE, x1 = xv.y + dv.y * INV_SCALE;
        float x2 = xv.z + dv.z * INV_SCALE, x3 = xv.w + dv.w * INV_SCALE;
        float s = x0 + x1 + x2 + x3;
        float q = x0 * x0 + x1 * x1 + x2 * x2 + x3 * x3;
#pragma unroll
        for (int off = 16; off; off >>= 1) {
            s += __shfl_xor_sync(0xffffffffu, s, off);
            q += __shfl_xor_sync(0xffffffffu, q, off);
        }
        float mean = s * (1.0f / 128.0f);
        float var = q * (1.0f / 128.0f) - mean * mean;
        float rs = rsqrtf(var + EPSLN);
        float4 o;
        o.x = g1[c0 + 0] * (x0 - mean) * rs + b1[c0 + 0];
        o.y = g1[c0 + 1] * (x1 - mean) * rs + b1[c0 + 1];
        o.z = g1[c0 + 2] * (x2 - mean) * rs + b1[c0 + 2];
        o.w = g1[c0 + 3] * (x3 - mean) * rs + b1[c0 + 3];
        *(float4*)(V1s + r * CC + c0) = o;
    }
    __syncthreads();
    for (int ct = 0; ct < 4; ++ct) {
        if (ct) __syncthreads();
        for (int e = tid; e < 4096; e += 512) {
            int k = e >> 5, cq = e & 31;
            ((float4*)Ws)[e] = ((const float4*)Win_w)[k * 128 + ct * 32 + cq];
        }
        __syncthreads();
        float acc[2][4];
#pragma unroll
        for (int j = 0; j < 4; ++j) {
            float b = Win_b[ct * 128 + c0 + j];
            acc[0][j] = b; acc[1][j] = b;
        }
        mm_tile<2>(acc, V1s, 32, Ws, r0, lane);
#pragma unroll
        for (int i = 0; i < 2; ++i)
#pragma unroll
            for (int j = 0; j < 4; ++j)
                Ts[(r0 + i) * FFD + ct * 128 + c0 + j] = gelu_f(acc[i][j]);
    }
    __syncthreads();
    float acc[2][4];
#pragma unroll
    for (int j = 0; j < 4; ++j) {
        float b = Wout_b[c0 + j];
        acc[0][j] = b; acc[1][j] = b;
    }
    for (int kt = 0; kt < 4; ++kt) {
        if (kt) __syncthreads();
        for (int e = tid; e < 4096; e += 512)
            ((float4*)Ws)[e] = ((const float4*)Wout_w)[kt * 4096 + e];
        __syncthreads();
        mm_tile<2>(acc, Ts + kt * 128, 128, Ws, r0, lane);
    }
#pragma unroll
    for (int i = 0; i < 2; ++i) {
        int r = r0 + i;
        float v0 = V1s[r * CC + c0 + 0] + acc[i][0];
        float v1 = V1s[r * CC + c0 + 1] + acc[i][1];
        float v2 = V1s[r * CC + c0 + 2] + acc[i][2];
        float v3 = V1s[r * CC + c0 + 3] + acc[i][3];
        float s = v0 + v1 + v2 + v3;
        float q = v0 * v0 + v1 * v1 + v2 * v2 + v3 * v3;
#pragma unroll
        for (int off = 16; off; off >>= 1) {
            s += __shfl_xor_sync(0xffffffffu, s, off);
            q += __shfl_xor_sync(0xffffffffu, q, off);
        }
        float mean = s * (1.0f / 128.0f);
        float var = q * (1.0f / 128.0f) - mean * mean;
        float rs = rsqrtf(var + EPSLN);
        float mv = mask_V[blockIdx.x * 32 + r];
        float4 o;
        o.x = (g2[c0 + 0] * (v0 - mean) * rs + b2[c0 + 0]) * mv;
        o.y = (g2[c0 + 1] * (v1 - mean) * rs + b2[c0 + 1]) * mv;
        o.z = (g2[c0 + 2] * (v2 - mean) * rs + b2[c0 + 2]) * mv;
        o.w = (g2[c0 + 3] * (v3 - mean) * rs + b2[c0 + 3]) * mv;
        *(float4*)(out + base + (size_t)r * CC + c0) = o;
    }
}

// ---------------------------------------------------------------------------
extern "C" void kernel_launch(void* const* d_in, const int* in_sizes, int n_in,
                              void* d_out, int out_size) {
    const float* h_V = (const float*)d_in[0];
    const float* h_E = (const float*)d_in[1];
    const int* E_idx = (const int*)d_in[2];
    const float* mask_V = (const float*)d_in[3];
    const float* mask_attend = (const float*)d_in[4];
    const float* W1_w = (const float*)d_in[5];
    const float* W1_b = (const float*)d_in[6];
    const float* W2_w = (const float*)d_in[7];
    const float* W2_b = (const float*)d_in[8];
    const float* W3_w = (const float*)d_in[9];
    const float* W3_b = (const float*)d_in[10];
    const float* W11_w = (const float*)d_in[11];
    const float* W11_b = (const float*)d_in[12];
    const float* W12_w = (const float*)d_in[13];
    const float* W12_b = (const float*)d_in[14];
    const float* W13_w = (const float*)d_in[15];
    const float* W13_b = (const float*)d_in[16];
    const float* Win_w = (const float*)d_in[17];
    const float* Win_b = (const float*)d_in[18];
    const float* Wout_w = (const float*)d_in[19];
    const float* Wout_b = (const float*)d_in[20];
    const float* g1 = (const float*)d_in[21];
    const float* b1 = (const float*)d_in[22];
    const float* g2 = (const float*)d_in[23];
    const float* b2 = (const float*)d_in[24];
    const float* g3 = (const float*)d_in[25];
    const float* b3 = (const float*)d_in[26];

    float* out_hV = (float*)d_out;
    float* out_hE = out_hV + (size_t)BN * CC;

    const int SMEM_PRE = (4096 + 16384) * 4;          // 80 KB
    const int SMEM_FFN = (4096 + 16384 + 16384) * 4;  // 144 KB

    cudaFuncSetAttribute(nodepre_kernel, cudaFuncAttributeMaxDynamicSharedMemorySize, SMEM_PRE);
    cudaFuncSetAttribute(ffn_kernel, cudaFuncAttributeMaxDynamicSharedMemorySize, SMEM_FFN);
    cudaFuncSetAttribute(edge_mma_kernel<false>, cudaFuncAttributeMaxDynamicSharedMemorySize, SMEM_EDGE_DYN);
    cudaFuncSetAttribute(edge_mma_kernel<true>, cudaFuncAttributeMaxDynamicSharedMemorySize, SMEM_EDGE_DYN);

    prep_weights<<<6, 256>>>(W1_w + CC * CC, W2_w, W3_w, W11_w + CC * CC, W12_w, W13_w);
    nodepre_kernel<<<BN / 32, 512, SMEM_PRE>>>(h_V, W1_w, W1_b);
    edge_mma_kernel<false><<<296, 384, SMEM_EDGE_DYN>>>(h_E, E_idx, mask_attend, 0,
                                                        W2_b, W3_b, g3, b3, out_hE);
    ffn_kernel<<<BN / 32, 512, SMEM_FFN>>>(h_V, Win_w, Win_b, Wout_w, Wout_b,
                                           g1, b1, g2, b2, mask_V, out_hV);
    nodepre_kernel<<<BN / 32, 512, SMEM_PRE>>>(out_hV, W11_w, W11_b);
    edge_mma_kernel<true><<<296, 384, SMEM_EDGE_DYN>>>(h_E, E_idx, mask_attend, 1,
                                                       W12_b, W13_b, g3, b3, out_hE);
}